// round 11
// baseline (speedup 1.0000x reference)
#include <cuda_runtime.h>
#include <cuda_fp16.h>
#include <stdint.h>
#include <math.h>

#define SEQ   2048
#define HID   4096
#define NH    32
#define NKV   8
#define HD    128
#define GRP   (NH / NKV)             // 4
#define QKVN  ((NH + 2 * NKV) * HD)  // 6144

// ---------------------------------------------------------------------------
// Scratch (device globals; no allocations allowed)
// ---------------------------------------------------------------------------
__device__ float g_qkv[SEQ * QKVN];        // QKV output, fp32
__device__ __half g_Ah[SEQ * HID];         // GEMM A hi (hs / attn-out)
__device__ __half g_Al[SEQ * HID];         // GEMM A lo
__device__ __half g_Bh[QKVN * HID];        // w_qkv^T fp16
__device__ __half g_Bh2[HID * HID];        // w_o^T fp16
__device__ __half g_Qh[NH * SEQ * HD];     // roped Q hi  [h][s][d]
__device__ __half g_Ql[NH * SEQ * HD];     // roped Q lo
__device__ __half g_Kh[NKV * SEQ * HD];    // roped K     [h][s][d]
__device__ __half g_Vh[NKV * SEQ * HD];    // V           [h][s][d]

// ---------------------------------------------------------------------------
// PTX helpers (portable: no 'a'-suffix features)
// ---------------------------------------------------------------------------
__device__ __forceinline__ uint32_t s2u(const void* p) {
    uint32_t a;
    asm("{ .reg .u64 t; cvta.to.shared.u64 t, %1; cvt.u32.u64 %0, t; }"
        : "=r"(a) : "l"(p));
    return a;
}

__device__ __forceinline__ void cpa16(uint32_t s, const void* g) {
    asm volatile("cp.async.cg.shared.global [%0], [%1], 16;" :: "r"(s), "l"(g));
}
__device__ __forceinline__ void cpa_commit() {
    asm volatile("cp.async.commit_group;" ::: "memory");
}
template <int N>
__device__ __forceinline__ void cpa_wait() {
    asm volatile("cp.async.wait_group %0;" :: "n"(N) : "memory");
}

__device__ __forceinline__ void ldm_x4(uint32_t* r, uint32_t addr) {
    asm volatile("ldmatrix.sync.aligned.m8n8.x4.shared.b16 {%0,%1,%2,%3}, [%4];"
                 : "=r"(r[0]), "=r"(r[1]), "=r"(r[2]), "=r"(r[3]) : "r"(addr));
}
__device__ __forceinline__ void ldm_x4t(uint32_t* r, uint32_t addr) {
    asm volatile("ldmatrix.sync.aligned.m8n8.x4.trans.shared.b16 {%0,%1,%2,%3}, [%4];"
                 : "=r"(r[0]), "=r"(r[1]), "=r"(r[2]), "=r"(r[3]) : "r"(addr));
}

// fp16 inputs, fp32 accumulate
__device__ __forceinline__ void mma16816(float* c, const uint32_t* a,
                                         uint32_t b0, uint32_t b1) {
    asm volatile(
        "mma.sync.aligned.m16n8k16.row.col.f32.f16.f16.f32 "
        "{%0,%1,%2,%3}, {%4,%5,%6,%7}, {%8,%9}, {%0,%1,%2,%3};"
        : "+f"(c[0]), "+f"(c[1]), "+f"(c[2]), "+f"(c[3])
        : "r"(a[0]), "r"(a[1]), "r"(a[2]), "r"(a[3]), "r"(b0), "r"(b1));
}

// ---------------------------------------------------------------------------
// Split fp32 -> fp16 hi + lo (elementwise, float4)
// ---------------------------------------------------------------------------
__global__ void split_kernel(const float* __restrict__ in,
                             __half* __restrict__ hi,
                             __half* __restrict__ lo, int n4)
{
    int i = blockIdx.x * blockDim.x + threadIdx.x;
    if (i >= n4) return;
    float4 v = ((const float4*)in)[i];
    __half h0 = __float2half_rn(v.x);
    __half h1 = __float2half_rn(v.y);
    __half h2 = __float2half_rn(v.z);
    __half h3 = __float2half_rn(v.w);
    __half l0 = __float2half_rn(v.x - __half2float(h0));
    __half l1 = __float2half_rn(v.y - __half2float(h1));
    __half l2 = __float2half_rn(v.z - __half2float(h2));
    __half l3 = __float2half_rn(v.w - __half2float(h3));
    __half2* hp = (__half2*)hi;
    __half2* lp = (__half2*)lo;
    hp[2 * i]     = __halves2half2(h0, h1);
    hp[2 * i + 1] = __halves2half2(h2, h3);
    lp[2 * i]     = __halves2half2(l0, l1);
    lp[2 * i + 1] = __halves2half2(l2, l3);
}

// ---------------------------------------------------------------------------
// Transpose + fp16 round (hi only): fp32 [K,N] row-major -> fp16 [N,K]
// ---------------------------------------------------------------------------
__global__ void transT_kernel(const float* __restrict__ in,
                              __half* __restrict__ hi, int K, int N)
{
    __shared__ float t[32][33];
    int n0 = blockIdx.x * 32, k0 = blockIdx.y * 32;
    int tx = threadIdx.x, ty = threadIdx.y;   // 32 x 8
#pragma unroll
    for (int j = 0; j < 4; j++)
        t[ty + 8 * j][tx] = in[(size_t)(k0 + ty + 8 * j) * N + n0 + tx];
    __syncthreads();
#pragma unroll
    for (int j = 0; j < 4; j++) {
        float a = t[tx][ty + 8 * j];
        hi[(size_t)(n0 + ty + 8 * j) * K + k0 + tx] = __float2half_rn(a);
    }
}

// ---------------------------------------------------------------------------
// mma.sync GEMM, fp16 2-term: C = Ah*Bh + Al*Bh.
// CTA 128x128, KC=64, 3-stage cp.async pipeline.
// Warp tile 32x64 (wm=warp>>1, wn=warp&1); B fragments via ldmatrix.x4.
// ---------------------------------------------------------------------------
#define KC      64
#define PITCH_B 144
#define TILE_SB (128 * PITCH_B)
#define STAGE_B (3 * TILE_SB)            // 55296
#define GEMM_SMEM (3 * STAGE_B)          // 165888

__global__ __launch_bounds__(256, 1)
void gemm_mma_kernel(const __half* __restrict__ Ah,
                     const __half* __restrict__ Al,
                     const __half* __restrict__ Bh,
                     float* __restrict__ C, int K, int Nc)
{
    extern __shared__ char smc[];
    const uint32_t sbase = s2u(smc);

    const int tid  = threadIdx.x;
    const int lane = tid & 31;
    const int warp = tid >> 5;
    const int wm = warp >> 1;            // 0..3 (32-row groups)
    const int wn = warp & 1;             // 0..1 (64-col groups)
    const int bm = blockIdx.y, bn = blockIdx.x;
    const int nchunk = K / KC;

    const __half* gsrc[3] = {Ah, Al, Bh};
    const int row0[3] = {bm * 128, bm * 128, bn * 128};

    auto load_stage = [&](int c, int s) {
        uint32_t stg = sbase + s * STAGE_B;
        int kt = c * KC;
#pragma unroll
        for (int j = 0; j < 12; ++j) {
            int idx  = tid + j * 256;
            int tsel = idx >> 10;
            int w    = idx & 1023;
            int r    = w >> 3;
            int ck   = w & 7;
            cpa16(stg + tsel * TILE_SB + r * PITCH_B + ck * 16,
                  gsrc[tsel] + (size_t)(row0[tsel] + r) * K + kt + ck * 8);
        }
    };

    float acc[2][8][4];
#pragma unroll
    for (int i = 0; i < 2; i++)
#pragma unroll
        for (int j = 0; j < 8; j++)
#pragma unroll
            for (int q = 0; q < 4; q++) acc[i][j][q] = 0.f;

    load_stage(0, 0); cpa_commit();
    load_stage(1, 1); cpa_commit();

    int scur = 0, sload = 2;
    for (int c = 0; c < nchunk; ++c) {
        cpa_wait<1>();
        __syncthreads();

        if (c + 2 < nchunk) {
            load_stage(c + 2, sload);
            cpa_commit();
        }

        uint32_t stg = sbase + scur * STAGE_B;
        uint32_t aBaseH = stg + (wm * 32 + (lane & 15)) * PITCH_B + (lane >> 4) * 16;
        uint32_t aBaseL = aBaseH + TILE_SB;
        uint32_t bBase  = stg + 2 * TILE_SB +
                          (wn * 64 + (lane & 15)) * PITCH_B + (lane >> 4) * 16;

#pragma unroll
        for (int s = 0; s < 4; ++s) {
            uint32_t ah[2][4], al[2][4], bx[4][4];
#pragma unroll
            for (int i = 0; i < 2; ++i) {
                ldm_x4(ah[i], aBaseH + i * 16 * PITCH_B + s * 32);
                ldm_x4(al[i], aBaseL + i * 16 * PITCH_B + s * 32);
            }
#pragma unroll
            for (int j2 = 0; j2 < 4; ++j2)
                ldm_x4(bx[j2], bBase + j2 * 16 * PITCH_B + s * 32);
#pragma unroll
            for (int i = 0; i < 2; ++i)
#pragma unroll
                for (int j2 = 0; j2 < 4; ++j2) {
                    // x4 B pairing: frag(2*j2)   = (r0, r2)
                    //               frag(2*j2+1) = (r1, r3)
                    mma16816(acc[i][2 * j2],     ah[i], bx[j2][0], bx[j2][2]);
                    mma16816(acc[i][2 * j2],     al[i], bx[j2][0], bx[j2][2]);
                    mma16816(acc[i][2 * j2 + 1], ah[i], bx[j2][1], bx[j2][3]);
                    mma16816(acc[i][2 * j2 + 1], al[i], bx[j2][1], bx[j2][3]);
                }
        }

        scur = (scur == 2) ? 0 : scur + 1;
        sload = (sload == 2) ? 0 : sload + 1;
    }

    const int rbase = bm * 128 + wm * 32 + (lane >> 2);
    const int cbase = bn * 128 + wn * 64 + (lane & 3) * 2;
#pragma unroll
    for (int i = 0; i < 2; ++i) {
#pragma unroll
        for (int j = 0; j < 8; ++j) {
            int r = rbase + i * 16;
            int col = cbase + j * 8;
            *(float2*)&C[(size_t)r * Nc + col] =
                make_float2(acc[i][j][0], acc[i][j][1]);
            *(float2*)&C[(size_t)(r + 8) * Nc + col] =
                make_float2(acc[i][j][2], acc[i][j][3]);
        }
    }
}

// ---------------------------------------------------------------------------
// RoPE + fp16 split: fp32 qkv -> Qh/Ql (scaled), Kh, Vh in [h][s][d].
// ---------------------------------------------------------------------------
__global__ void rope_split_kernel(const float* __restrict__ qkv,
                                  const int* __restrict__ positions,
                                  __half* __restrict__ Qh, __half* __restrict__ Ql,
                                  __half* __restrict__ Kh, __half* __restrict__ Vh)
{
    int idx = blockIdx.x * blockDim.x + threadIdx.x;
    const int NHTOT = NH + 2 * NKV;  // 48
    const int TOTAL = SEQ * NHTOT * (HD / 2);
    if (idx >= TOTAL) return;

    int d = idx & 63;
    int h = (idx >> 6) % NHTOT;
    int s = idx / (NHTOT * 64);

    const float* base = qkv + (size_t)s * QKVN + h * HD;
    float x1 = base[d];
    float x2 = base[d + 64];
    float y1 = x1, y2 = x2;

    if (h < NH + NKV) {
        float pos = (float)positions[s];
        float inv = powf(10000.0f, -(2.0f * (float)d) / (float)HD);
        float ang = pos * inv;
        float c, sn;
        sincosf(ang, &sn, &c);
        y1 = x1 * c - x2 * sn;
        y2 = x2 * c + x1 * sn;
    }

    if (h < NH) {
        const float scale = 0.088388347648318447f;  // 1/sqrt(128)
        y1 *= scale; y2 *= scale;
        size_t off = ((size_t)h * SEQ + s) * HD + d;
        __half h1 = __float2half_rn(y1);
        __half h2 = __float2half_rn(y2);
        Qh[off]      = h1;
        Qh[off + 64] = h2;
        Ql[off]      = __float2half_rn(y1 - __half2float(h1));
        Ql[off + 64] = __float2half_rn(y2 - __half2float(h2));
    } else if (h < NH + NKV) {
        size_t off = ((size_t)(h - NH) * SEQ + s) * HD + d;
        Kh[off]      = __float2half_rn(y1);
        Kh[off + 64] = __float2half_rn(y2);
    } else {
        size_t off = ((size_t)(h - NH - NKV) * SEQ + s) * HD + d;
        Vh[off]      = __float2half_rn(y1);
        Vh[off + 64] = __float2half_rn(y2);
    }
}

// ---------------------------------------------------------------------------
// Tensor-core flash attention (fp16 2-term), causal, GQA. Br=Bc=64, 256 thr.
// S = Qh*Kh + Ql*Kh ; O = Ph*Vh + Pl*Vh. Double-buffered K/V; x4 ldmatrix.
// ---------------------------------------------------------------------------
#define APITCH 272
#define PPITCH 144
#define SSP    68
#define ATILE  (64 * APITCH)            // 17408
#define KVSTG  (2 * ATILE)              // 34816 (KH,VH)
#define O_QH   0
#define O_QL   (O_QH + ATILE)
#define O_KV0  (O_QL + ATILE)           // 34816
#define O_SS   (O_KV0 + 2 * KVSTG)      // 104448
#define O_PH   (O_SS + 64 * SSP * 4)    // 121856
#define O_PL   (O_PH + 64 * PPITCH)     // 131072
#define O_CORR (O_PL + 64 * PPITCH)     // 140288
#define O_LINV (O_CORR + 256)
#define FL_SMEM (O_LINV + 256)          // 140800

__global__ __launch_bounds__(256, 1)
void flash_mma_kernel(const __half* __restrict__ Qh, const __half* __restrict__ Ql,
                      const __half* __restrict__ Kh, const __half* __restrict__ Vh,
                      __half* __restrict__ outH, __half* __restrict__ outL)
{
    extern __shared__ char smx[];
    const uint32_t sb = s2u(smx);
    float* SsF  = (float*)(smx + O_SS);
    float* corr = (float*)(smx + O_CORR);
    float* linv = (float*)(smx + O_LINV);

    const int qb = (int)gridDim.x - 1 - (int)blockIdx.x;  // longest first
    const int h  = blockIdx.y;
    const int kvh = h / GRP;

    const int tid  = threadIdx.x;
    const int warp = tid >> 5;
    const int lane = tid & 31;
    const int wr = warp & 3;
    const int wc = warp >> 2;

    const __half* kH = Kh + (size_t)kvh * SEQ * HD;
    const __half* vH = Vh + (size_t)kvh * SEQ * HD;
    const __half* kvsrc[2] = {kH, vH};

    auto load_kv = [&](int kb, int buf) {
#pragma unroll
        for (int j = 0; j < 8; ++j) {
            int idx = tid + j * 256;
            int tsel = idx >> 10;
            int w = idx & 1023;
            int r = w >> 4, ck = w & 15;
            cpa16(sb + O_KV0 + buf * KVSTG + tsel * ATILE + r * APITCH + ck * 16,
                  kvsrc[tsel] + ((size_t)(kb * 64 + r)) * HD + ck * 8);
        }
    };

    // --- prologue: Q tiles + KV block 0 ---
    {
        const __half* qH = Qh + ((size_t)h * SEQ + qb * 64) * HD;
        const __half* qL = Ql + ((size_t)h * SEQ + qb * 64) * HD;
#pragma unroll
        for (int j = 0; j < 8; ++j) {
            int idx = tid + j * 256;
            int tsel = idx >> 10;
            int w = idx & 1023;
            int r = w >> 4, ck = w & 15;
            cpa16(sb + (tsel ? O_QL : O_QH) + r * APITCH + ck * 16,
                  (tsel ? qL : qH) + (size_t)r * HD + ck * 8);
        }
        cpa_commit();
    }
    load_kv(0, 0);
    cpa_commit();

    float m_i[8], l_i[8], oacc[8][4];
#pragma unroll
    for (int r = 0; r < 8; ++r) { m_i[r] = -1e30f; l_i[r] = 0.f; }
#pragma unroll
    for (int t = 0; t < 8; ++t)
#pragma unroll
        for (int q = 0; q < 4; ++q) oacc[t][q] = 0.f;

    for (int kb = 0; kb <= qb; ++kb) {
        const int buf = kb & 1;
        cpa_wait<0>();
        __syncthreads();

        if (kb + 1 <= qb) {
            load_kv(kb + 1, buf ^ 1);
            cpa_commit();
        }

        const uint32_t kvb = sb + O_KV0 + buf * KVSTG;

        // ---- QK: S = Qh*Kh + Ql*Kh ----
        float sf[4][4];
#pragma unroll
        for (int j = 0; j < 4; ++j)
#pragma unroll
            for (int q = 0; q < 4; ++q) sf[j][q] = 0.f;

        uint32_t aH = sb + O_QH + (wr * 16 + (lane & 15)) * APITCH + (lane >> 4) * 16;
        uint32_t aL = aH + ATILE;
        uint32_t bK = kvb + (wc * 32 + (lane & 15)) * APITCH + (lane >> 4) * 16;
#pragma unroll
        for (int s = 0; s < 8; ++s) {
            uint32_t qh4[4], ql4[4], kx[2][4];
            ldm_x4(qh4, aH + s * 32);
            ldm_x4(ql4, aL + s * 32);
#pragma unroll
            for (int j2 = 0; j2 < 2; ++j2)
                ldm_x4(kx[j2], bK + j2 * 16 * APITCH + s * 32);
#pragma unroll
            for (int j2 = 0; j2 < 2; ++j2) {
                mma16816(sf[2 * j2],     qh4, kx[j2][0], kx[j2][2]);
                mma16816(sf[2 * j2],     ql4, kx[j2][0], kx[j2][2]);
                mma16816(sf[2 * j2 + 1], qh4, kx[j2][1], kx[j2][3]);
                mma16816(sf[2 * j2 + 1], ql4, kx[j2][1], kx[j2][3]);
            }
        }

        // store S to smem with causal mask
        {
            int r0 = wr * 16 + (lane >> 2);
            int c0 = wc * 32 + (lane & 3) * 2;
            bool diag = (kb == qb);
#pragma unroll
            for (int j = 0; j < 4; ++j) {
                int c = c0 + j * 8;
                float v0 = sf[j][0], v1 = sf[j][1], v2 = sf[j][2], v3 = sf[j][3];
                if (diag) {
                    if (c > r0)         v0 = -1e30f;
                    if (c + 1 > r0)     v1 = -1e30f;
                    if (c > r0 + 8)     v2 = -1e30f;
                    if (c + 1 > r0 + 8) v3 = -1e30f;
                }
                SsF[r0 * SSP + c]           = v0;
                SsF[r0 * SSP + c + 1]       = v1;
                SsF[(r0 + 8) * SSP + c]     = v2;
                SsF[(r0 + 8) * SSP + c + 1] = v3;
            }
        }
        __syncthreads();

        // ---- softmax on owner rows ----
#pragma unroll
        for (int rr = 0; rr < 8; ++rr) {
            int r = warp * 8 + rr;
            float s0 = SsF[r * SSP + lane];
            float s1 = SsF[r * SSP + lane + 32];
            float mx = fmaxf(s0, s1);
#pragma unroll
            for (int o = 16; o > 0; o >>= 1)
                mx = fmaxf(mx, __shfl_xor_sync(0xFFFFFFFFu, mx, o));
            float m_new = fmaxf(m_i[rr], mx);
            float p0 = __expf(s0 - m_new);
            float p1 = __expf(s1 - m_new);
            SsF[r * SSP + lane]      = p0;
            SsF[r * SSP + lane + 32] = p1;
            float sum = p0 + p1;
#pragma unroll
            for (int o = 16; o > 0; o >>= 1)
                sum += __shfl_xor_sync(0xFFFFFFFFu, sum, o);
            float crr = __expf(m_i[rr] - m_new);
            l_i[rr] = l_i[rr] * crr + sum;
            m_i[rr] = m_new;
            if (lane == 0) corr[r] = crr;
        }
        __syncthreads();

        // ---- convert P -> fp16 hi/lo; scale O accumulators ----
#pragma unroll
        for (int j = 0; j < 8; ++j) {
            int i = tid + j * 256;
            int r = i >> 5;
            int c2 = (i & 31) * 2;
            float p0 = SsF[r * SSP + c2];
            float p1 = SsF[r * SSP + c2 + 1];
            __half h0 = __float2half_rn(p0);
            __half h1 = __float2half_rn(p1);
            *(__half2*)(smx + O_PH + r * PPITCH + c2 * 2) = __halves2half2(h0, h1);
            *(__half2*)(smx + O_PL + r * PPITCH + c2 * 2) =
                __halves2half2(__float2half_rn(p0 - __half2float(h0)),
                               __float2half_rn(p1 - __half2float(h1)));
        }
        {
            float cr0 = corr[wr * 16 + (lane >> 2)];
            float cr1 = corr[wr * 16 + (lane >> 2) + 8];
#pragma unroll
            for (int t = 0; t < 8; ++t) {
                oacc[t][0] *= cr0; oacc[t][1] *= cr0;
                oacc[t][2] *= cr1; oacc[t][3] *= cr1;
            }
        }
        __syncthreads();

        // ---- PV: O += Ph*Vh + Pl*Vh ----
        {
            uint32_t pH = sb + O_PH + (wr * 16 + (lane & 15)) * PPITCH + (lane >> 4) * 16;
            uint32_t pL = pH + (O_PL - O_PH);
            uint32_t vB = kvb + ATILE + (lane & 15) * APITCH + (lane >> 4) * 16 + wc * 128;
#pragma unroll
            for (int s = 0; s < 4; ++s) {
                uint32_t ph4[4], pl4[4], vx[4][4];
                ldm_x4(ph4, pH + s * 32);
                ldm_x4(pl4, pL + s * 32);
#pragma unroll
                for (int j2 = 0; j2 < 4; ++j2)
                    ldm_x4t(vx[j2], vB + s * 16 * APITCH + j2 * 32);
#pragma unroll
                for (int j2 = 0; j2 < 4; ++j2) {
                    // x4.trans pairing: frag(2*j2) = (r0,r1), frag(2*j2+1) = (r2,r3)
                    mma16816(oacc[2 * j2],     ph4, vx[j2][0], vx[j2][1]);
                    mma16816(oacc[2 * j2],     pl4, vx[j2][0], vx[j2][1]);
                    mma16816(oacc[2 * j2 + 1], ph4, vx[j2][2], vx[j2][3]);
                    mma16816(oacc[2 * j2 + 1], pl4, vx[j2][2], vx[j2][3]);
                }
            }
        }
    }

    // ---- epilogue ----
    __syncthreads();
    if (lane == 0) {
#pragma unroll
        for (int rr = 0; rr < 8; ++rr)
            linv[warp * 8 + rr] = 1.f / l_i[rr];
    }
    __syncthreads();

    {
        float li0 = linv[wr * 16 + (lane >> 2)];
        float li1 = linv[wr * 16 + (lane >> 2) + 8];
        int orow = qb * 64 + wr * 16 + (lane >> 2);
        int ocol = h * HD + wc * 64 + (lane & 3) * 2;
#pragma unroll
        for (int j = 0; j < 8; ++j) {
            int c = ocol + j * 8;
            float f0 = oacc[j][0] * li0, f1 = oacc[j][1] * li0;
            float f2 = oacc[j][2] * li1, f3 = oacc[j][3] * li1;
            __half h0 = __float2half_rn(f0);
            __half h1 = __float2half_rn(f1);
            __half h2 = __float2half_rn(f2);
            __half h3 = __float2half_rn(f3);
            *(__half2*)&outH[(size_t)orow * HID + c] = __halves2half2(h0, h1);
            *(__half2*)&outL[(size_t)orow * HID + c] =
                __halves2half2(__float2half_rn(f0 - __half2float(h0)),
                               __float2half_rn(f1 - __half2float(h1)));
            *(__half2*)&outH[(size_t)(orow + 8) * HID + c] = __halves2half2(h2, h3);
            *(__half2*)&outL[(size_t)(orow + 8) * HID + c] =
                __halves2half2(__float2half_rn(f2 - __half2float(h2)),
                               __float2half_rn(f3 - __half2float(h3)));
        }
    }
}

// ---------------------------------------------------------------------------
// kernel_launch
// ---------------------------------------------------------------------------
extern "C" void kernel_launch(void* const* d_in, const int* in_sizes, int n_in,
                              void* d_out, int out_size)
{
    const float* hs    = (const float*)d_in[0];
    const int*   pos   = (const int*)d_in[1];
    const float* w_qkv = (const float*)d_in[2];
    const float* w_o   = (const float*)d_in[3];
    float* out = (float*)d_out;

    float* qkv; cudaGetSymbolAddress((void**)&qkv, g_qkv);
    __half *Ah, *Al, *Bh, *Bh2, *Qh, *Ql, *Kh, *Vh;
    cudaGetSymbolAddress((void**)&Ah, g_Ah);
    cudaGetSymbolAddress((void**)&Al, g_Al);
    cudaGetSymbolAddress((void**)&Bh, g_Bh);
    cudaGetSymbolAddress((void**)&Bh2, g_Bh2);
    cudaGetSymbolAddress((void**)&Qh, g_Qh);
    cudaGetSymbolAddress((void**)&Ql, g_Ql);
    cudaGetSymbolAddress((void**)&Kh, g_Kh);
    cudaGetSymbolAddress((void**)&Vh, g_Vh);

    cudaFuncSetAttribute(gemm_mma_kernel,
                         cudaFuncAttributeMaxDynamicSharedMemorySize, GEMM_SMEM);
    cudaFuncSetAttribute(flash_mma_kernel,
                         cudaFuncAttributeMaxDynamicSharedMemorySize, FL_SMEM);

    // 1) split hs ; transpose both weight matrices (w_o into its own buffer)
    split_kernel<<<(SEQ * HID / 4 + 255) / 256, 256>>>(hs, Ah, Al, SEQ * HID / 4);
    transT_kernel<<<dim3(QKVN / 32, HID / 32), dim3(32, 8)>>>(w_qkv, Bh, HID, QKVN);
    transT_kernel<<<dim3(HID / 32, HID / 32), dim3(32, 8)>>>(w_o, Bh2, HID, HID);

    // 2) QKV projection (tensor cores, fp16 2-term)
    gemm_mma_kernel<<<dim3(QKVN / 128, SEQ / 128), 256, GEMM_SMEM>>>(
        Ah, Al, Bh, qkv, HID, QKVN);

    // 3) RoPE + split into fp16 Q(hi/lo)/K/V [h][s][d]
    {
        int total = SEQ * (NH + 2 * NKV) * (HD / 2);
        rope_split_kernel<<<(total + 255) / 256, 256>>>(qkv, pos, Qh, Ql, Kh, Vh);
    }

    // 4) Tensor-core flash attention -> fp16 hi/lo directly into Ah/Al
    flash_mma_kernel<<<dim3(SEQ / 64, NH), 256, FL_SMEM>>>(
        Qh, Ql, Kh, Vh, Ah, Al);

    // 5) Output projection (tensor cores, fp16 2-term)
    gemm_mma_kernel<<<dim3(HID / 128, SEQ / 128), 256, GEMM_SMEM>>>(
        Ah, Al, Bh2, out, HID, HID);
}

// round 12
// speedup vs baseline: 1.1661x; 1.1661x over previous
#include <cuda_runtime.h>
#include <cuda_fp16.h>
#include <stdint.h>
#include <math.h>

#define SEQ   2048
#define HID   4096
#define NH    32
#define NKV   8
#define HD    128
#define GRP   (NH / NKV)             // 4
#define QKVN  ((NH + 2 * NKV) * HD)  // 6144

// ---------------------------------------------------------------------------
// Scratch (device globals; no allocations allowed)
// ---------------------------------------------------------------------------
__device__ float g_qkv[SEQ * QKVN];        // QKV output, fp32
__device__ __half g_Ah[SEQ * HID];         // GEMM A hi (hs / attn-out)
__device__ __half g_Al[SEQ * HID];         // GEMM A lo
__device__ __half g_Bh[QKVN * HID];        // w_qkv^T fp16
__device__ __half g_Bh2[HID * HID];        // w_o^T fp16
__device__ __half g_Qh[NH * SEQ * HD];     // roped Q hi  [h][s][d]
__device__ __half g_Ql[NH * SEQ * HD];     // roped Q lo
__device__ __half g_Kh[NKV * SEQ * HD];    // roped K     [h][s][d]
__device__ __half g_Vh[NKV * SEQ * HD];    // V           [h][s][d]

// ---------------------------------------------------------------------------
// PTX helpers (portable: no 'a'-suffix features)
// ---------------------------------------------------------------------------
__device__ __forceinline__ uint32_t s2u(const void* p) {
    uint32_t a;
    asm("{ .reg .u64 t; cvta.to.shared.u64 t, %1; cvt.u32.u64 %0, t; }"
        : "=r"(a) : "l"(p));
    return a;
}

__device__ __forceinline__ void cpa16(uint32_t s, const void* g) {
    asm volatile("cp.async.cg.shared.global [%0], [%1], 16;" :: "r"(s), "l"(g));
}
__device__ __forceinline__ void cpa_commit() {
    asm volatile("cp.async.commit_group;" ::: "memory");
}
template <int N>
__device__ __forceinline__ void cpa_wait() {
    asm volatile("cp.async.wait_group %0;" :: "n"(N) : "memory");
}

__device__ __forceinline__ void ldm_x4(uint32_t* r, uint32_t addr) {
    asm volatile("ldmatrix.sync.aligned.m8n8.x4.shared.b16 {%0,%1,%2,%3}, [%4];"
                 : "=r"(r[0]), "=r"(r[1]), "=r"(r[2]), "=r"(r[3]) : "r"(addr));
}
__device__ __forceinline__ void ldm_x2(uint32_t* r, uint32_t addr) {
    asm volatile("ldmatrix.sync.aligned.m8n8.x2.shared.b16 {%0,%1}, [%2];"
                 : "=r"(r[0]), "=r"(r[1]) : "r"(addr));
}
__device__ __forceinline__ void ldm_x2t(uint32_t* r, uint32_t addr) {
    asm volatile("ldmatrix.sync.aligned.m8n8.x2.trans.shared.b16 {%0,%1}, [%2];"
                 : "=r"(r[0]), "=r"(r[1]) : "r"(addr));
}

// fp16 inputs, fp32 accumulate
__device__ __forceinline__ void mma16816(float* c, const uint32_t* a,
                                         uint32_t b0, uint32_t b1) {
    asm volatile(
        "mma.sync.aligned.m16n8k16.row.col.f32.f16.f16.f32 "
        "{%0,%1,%2,%3}, {%4,%5,%6,%7}, {%8,%9}, {%0,%1,%2,%3};"
        : "+f"(c[0]), "+f"(c[1]), "+f"(c[2]), "+f"(c[3])
        : "r"(a[0]), "r"(a[1]), "r"(a[2]), "r"(a[3]), "r"(b0), "r"(b1));
}

// ---------------------------------------------------------------------------
// Split fp32 -> fp16 hi + lo (elementwise, float4)
// ---------------------------------------------------------------------------
__global__ void split_kernel(const float* __restrict__ in,
                             __half* __restrict__ hi,
                             __half* __restrict__ lo, int n4)
{
    int i = blockIdx.x * blockDim.x + threadIdx.x;
    if (i >= n4) return;
    float4 v = ((const float4*)in)[i];
    __half h0 = __float2half_rn(v.x);
    __half h1 = __float2half_rn(v.y);
    __half h2 = __float2half_rn(v.z);
    __half h3 = __float2half_rn(v.w);
    __half l0 = __float2half_rn(v.x - __half2float(h0));
    __half l1 = __float2half_rn(v.y - __half2float(h1));
    __half l2 = __float2half_rn(v.z - __half2float(h2));
    __half l3 = __float2half_rn(v.w - __half2float(h3));
    __half2* hp = (__half2*)hi;
    __half2* lp = (__half2*)lo;
    hp[2 * i]     = __halves2half2(h0, h1);
    hp[2 * i + 1] = __halves2half2(h2, h3);
    lp[2 * i]     = __halves2half2(l0, l1);
    lp[2 * i + 1] = __halves2half2(l2, l3);
}

// ---------------------------------------------------------------------------
// Transpose + fp16 round (hi only): fp32 [K,N] row-major -> fp16 [N,K]
// ---------------------------------------------------------------------------
__global__ void transT_kernel(const float* __restrict__ in,
                              __half* __restrict__ hi, int K, int N)
{
    __shared__ float t[32][33];
    int n0 = blockIdx.x * 32, k0 = blockIdx.y * 32;
    int tx = threadIdx.x, ty = threadIdx.y;   // 32 x 8
#pragma unroll
    for (int j = 0; j < 4; j++)
        t[ty + 8 * j][tx] = in[(size_t)(k0 + ty + 8 * j) * N + n0 + tx];
    __syncthreads();
#pragma unroll
    for (int j = 0; j < 4; j++) {
        float a = t[tx][ty + 8 * j];
        hi[(size_t)(n0 + ty + 8 * j) * K + k0 + tx] = __float2half_rn(a);
    }
}

// ---------------------------------------------------------------------------
// mma.sync GEMM, fp16 2-term: C = Ah*Bh + Al*Bh.
// CTA 128x128, KC=64, 2-stage cp.async pipeline, 2 CTAs/SM.
// Warp tile 64x32 (round-9 proven shape).
// ---------------------------------------------------------------------------
#define KC      64
#define PITCH_B 144
#define TILE_SB (128 * PITCH_B)
#define STAGE_B (3 * TILE_SB)            // 55296
#define GEMM_SMEM (2 * STAGE_B)          // 110592 -> 2 CTAs/SM

__global__ __launch_bounds__(256, 2)
void gemm_mma_kernel(const __half* __restrict__ Ah,
                     const __half* __restrict__ Al,
                     const __half* __restrict__ Bh,
                     float* __restrict__ C, int K, int Nc)
{
    extern __shared__ char smc[];
    const uint32_t sbase = s2u(smc);

    const int tid  = threadIdx.x;
    const int lane = tid & 31;
    const int warp = tid >> 5;
    const int wm = warp >> 2;            // 0..1 (64-row halves)
    const int wn = warp & 3;             // 0..3 (32-col quarters)
    const int bm = blockIdx.y, bn = blockIdx.x;
    const int nchunk = K / KC;

    const __half* gsrc[3] = {Ah, Al, Bh};
    const int row0[3] = {bm * 128, bm * 128, bn * 128};

    auto load_stage = [&](int c, int s) {
        uint32_t stg = sbase + s * STAGE_B;
        int kt = c * KC;
#pragma unroll
        for (int j = 0; j < 12; ++j) {
            int idx  = tid + j * 256;
            int tsel = idx >> 10;
            int w    = idx & 1023;
            int r    = w >> 3;
            int ck   = w & 7;
            cpa16(stg + tsel * TILE_SB + r * PITCH_B + ck * 16,
                  gsrc[tsel] + (size_t)(row0[tsel] + r) * K + kt + ck * 8);
        }
    };

    float acc[4][4][4];
#pragma unroll
    for (int i = 0; i < 4; i++)
#pragma unroll
        for (int j = 0; j < 4; j++)
#pragma unroll
            for (int q = 0; q < 4; q++) acc[i][j][q] = 0.f;

    load_stage(0, 0);
    cpa_commit();

    for (int c = 0; c < nchunk; ++c) {
        if (c + 1 < nchunk) {
            load_stage(c + 1, (c + 1) & 1);
            cpa_commit();
            cpa_wait<1>();
        } else {
            cpa_wait<0>();
        }
        __syncthreads();

        uint32_t stg = sbase + (c & 1) * STAGE_B;
        uint32_t aBaseH = stg + (wm * 64 + (lane & 15)) * PITCH_B + (lane >> 4) * 16;
        uint32_t aBaseL = aBaseH + TILE_SB;
        uint32_t bBase  = stg + 2 * TILE_SB +
                          (wn * 32 + (lane & 7)) * PITCH_B + ((lane >> 3) & 1) * 16;

#pragma unroll
        for (int s = 0; s < 4; ++s) {
            uint32_t ah[4][4], al[4][4], bh[4][2];
#pragma unroll
            for (int i = 0; i < 4; ++i) {
                ldm_x4(ah[i], aBaseH + i * 16 * PITCH_B + s * 32);
                ldm_x4(al[i], aBaseL + i * 16 * PITCH_B + s * 32);
            }
#pragma unroll
            for (int j = 0; j < 4; ++j)
                ldm_x2(bh[j], bBase + j * 8 * PITCH_B + s * 32);
#pragma unroll
            for (int i = 0; i < 4; ++i)
#pragma unroll
                for (int j = 0; j < 4; ++j) {
                    mma16816(acc[i][j], ah[i], bh[j][0], bh[j][1]);
                    mma16816(acc[i][j], al[i], bh[j][0], bh[j][1]);
                }
        }
        __syncthreads();
    }

    const int rbase = bm * 128 + wm * 64 + (lane >> 2);
    const int cbase = bn * 128 + wn * 32 + (lane & 3) * 2;
#pragma unroll
    for (int i = 0; i < 4; ++i) {
#pragma unroll
        for (int j = 0; j < 4; ++j) {
            int r = rbase + i * 16;
            int col = cbase + j * 8;
            *(float2*)&C[(size_t)r * Nc + col] =
                make_float2(acc[i][j][0], acc[i][j][1]);
            *(float2*)&C[(size_t)(r + 8) * Nc + col] =
                make_float2(acc[i][j][2], acc[i][j][3]);
        }
    }
}

// ---------------------------------------------------------------------------
// RoPE + fp16 split: fp32 qkv -> Qh/Ql (scaled), Kh, Vh in [h][s][d].
// ---------------------------------------------------------------------------
__global__ void rope_split_kernel(const float* __restrict__ qkv,
                                  const int* __restrict__ positions,
                                  __half* __restrict__ Qh, __half* __restrict__ Ql,
                                  __half* __restrict__ Kh, __half* __restrict__ Vh)
{
    int idx = blockIdx.x * blockDim.x + threadIdx.x;
    const int NHTOT = NH + 2 * NKV;  // 48
    const int TOTAL = SEQ * NHTOT * (HD / 2);
    if (idx >= TOTAL) return;

    int d = idx & 63;
    int h = (idx >> 6) % NHTOT;
    int s = idx / (NHTOT * 64);

    const float* base = qkv + (size_t)s * QKVN + h * HD;
    float x1 = base[d];
    float x2 = base[d + 64];
    float y1 = x1, y2 = x2;

    if (h < NH + NKV) {
        float pos = (float)positions[s];
        float inv = powf(10000.0f, -(2.0f * (float)d) / (float)HD);
        float ang = pos * inv;
        float c, sn;
        sincosf(ang, &sn, &c);
        y1 = x1 * c - x2 * sn;
        y2 = x2 * c + x1 * sn;
    }

    if (h < NH) {
        const float scale = 0.088388347648318447f;  // 1/sqrt(128)
        y1 *= scale; y2 *= scale;
        size_t off = ((size_t)h * SEQ + s) * HD + d;
        __half h1 = __float2half_rn(y1);
        __half h2 = __float2half_rn(y2);
        Qh[off]      = h1;
        Qh[off + 64] = h2;
        Ql[off]      = __float2half_rn(y1 - __half2float(h1));
        Ql[off + 64] = __float2half_rn(y2 - __half2float(h2));
    } else if (h < NH + NKV) {
        size_t off = ((size_t)(h - NH) * SEQ + s) * HD + d;
        Kh[off]      = __float2half_rn(y1);
        Kh[off + 64] = __float2half_rn(y2);
    } else {
        size_t off = ((size_t)(h - NH - NKV) * SEQ + s) * HD + d;
        Vh[off]      = __float2half_rn(y1);
        Vh[off + 64] = __float2half_rn(y2);
    }
}

// ---------------------------------------------------------------------------
// Tensor-core flash attention (fp16 2-term), causal, GQA. Br=Bc=64, 256 thr.
// S = Qh*Kh + Ql*Kh ; O = Ph*Vh + Pl*Vh. Double-buffered K/V (round-9 proven).
// ---------------------------------------------------------------------------
#define APITCH 272
#define PPITCH 144
#define SSP    68
#define ATILE  (64 * APITCH)            // 17408
#define KVSTG  (2 * ATILE)              // 34816 (KH,VH)
#define O_QH   0
#define O_QL   (O_QH + ATILE)
#define O_KV0  (O_QL + ATILE)           // 34816
#define O_SS   (O_KV0 + 2 * KVSTG)      // 104448
#define O_PH   (O_SS + 64 * SSP * 4)    // 121856
#define O_PL   (O_PH + 64 * PPITCH)     // 131072
#define O_CORR (O_PL + 64 * PPITCH)     // 140288
#define O_LINV (O_CORR + 256)
#define FL_SMEM (O_LINV + 256)          // 140800

__global__ __launch_bounds__(256, 1)
void flash_mma_kernel(const __half* __restrict__ Qh, const __half* __restrict__ Ql,
                      const __half* __restrict__ Kh, const __half* __restrict__ Vh,
                      __half* __restrict__ outH, __half* __restrict__ outL)
{
    extern __shared__ char smx[];
    const uint32_t sb = s2u(smx);
    float* SsF  = (float*)(smx + O_SS);
    float* corr = (float*)(smx + O_CORR);
    float* linv = (float*)(smx + O_LINV);

    const int qb = (int)gridDim.x - 1 - (int)blockIdx.x;  // longest first
    const int h  = blockIdx.y;
    const int kvh = h / GRP;

    const int tid  = threadIdx.x;
    const int warp = tid >> 5;
    const int lane = tid & 31;
    const int wr = warp & 3;
    const int wc = warp >> 2;

    const __half* kH = Kh + (size_t)kvh * SEQ * HD;
    const __half* vH = Vh + (size_t)kvh * SEQ * HD;
    const __half* kvsrc[2] = {kH, vH};

    auto load_kv = [&](int kb, int buf) {
#pragma unroll
        for (int j = 0; j < 8; ++j) {
            int idx = tid + j * 256;
            int tsel = idx >> 10;
            int w = idx & 1023;
            int r = w >> 4, ck = w & 15;
            cpa16(sb + O_KV0 + buf * KVSTG + tsel * ATILE + r * APITCH + ck * 16,
                  kvsrc[tsel] + ((size_t)(kb * 64 + r)) * HD + ck * 8);
        }
    };

    // --- prologue: Q tiles + KV block 0 ---
    {
        const __half* qH = Qh + ((size_t)h * SEQ + qb * 64) * HD;
        const __half* qL = Ql + ((size_t)h * SEQ + qb * 64) * HD;
#pragma unroll
        for (int j = 0; j < 8; ++j) {
            int idx = tid + j * 256;
            int tsel = idx >> 10;
            int w = idx & 1023;
            int r = w >> 4, ck = w & 15;
            cpa16(sb + (tsel ? O_QL : O_QH) + r * APITCH + ck * 16,
                  (tsel ? qL : qH) + (size_t)r * HD + ck * 8);
        }
        cpa_commit();
    }
    load_kv(0, 0);
    cpa_commit();

    float m_i[8], l_i[8], oacc[8][4];
#pragma unroll
    for (int r = 0; r < 8; ++r) { m_i[r] = -1e30f; l_i[r] = 0.f; }
#pragma unroll
    for (int t = 0; t < 8; ++t)
#pragma unroll
        for (int q = 0; q < 4; ++q) oacc[t][q] = 0.f;

    for (int kb = 0; kb <= qb; ++kb) {
        const int buf = kb & 1;
        cpa_wait<0>();
        __syncthreads();

        if (kb + 1 <= qb) {
            load_kv(kb + 1, buf ^ 1);
            cpa_commit();
        }

        const uint32_t kvb = sb + O_KV0 + buf * KVSTG;

        // ---- QK: S = Qh*Kh + Ql*Kh ----
        float sf[4][4];
#pragma unroll
        for (int j = 0; j < 4; ++j)
#pragma unroll
            for (int q = 0; q < 4; ++q) sf[j][q] = 0.f;

        uint32_t aH = sb + O_QH + (wr * 16 + (lane & 15)) * APITCH + (lane >> 4) * 16;
        uint32_t aL = aH + ATILE;
        uint32_t bH = kvb + (wc * 32 + (lane & 7)) * APITCH + ((lane >> 3) & 1) * 16;
#pragma unroll
        for (int s = 0; s < 8; ++s) {
            uint32_t qh4[4], ql4[4];
            ldm_x4(qh4, aH + s * 32);
            ldm_x4(ql4, aL + s * 32);
#pragma unroll
            for (int j = 0; j < 4; ++j) {
                uint32_t kh2[2];
                ldm_x2(kh2, bH + j * 8 * APITCH + s * 32);
                mma16816(sf[j], qh4, kh2[0], kh2[1]);
                mma16816(sf[j], ql4, kh2[0], kh2[1]);
            }
        }

        // store S to smem with causal mask
        {
            int r0 = wr * 16 + (lane >> 2);
            int c0 = wc * 32 + (lane & 3) * 2;
            bool diag = (kb == qb);
#pragma unroll
            for (int j = 0; j < 4; ++j) {
                int c = c0 + j * 8;
                float v0 = sf[j][0], v1 = sf[j][1], v2 = sf[j][2], v3 = sf[j][3];
                if (diag) {
                    if (c > r0)         v0 = -1e30f;
                    if (c + 1 > r0)     v1 = -1e30f;
                    if (c > r0 + 8)     v2 = -1e30f;
                    if (c + 1 > r0 + 8) v3 = -1e30f;
                }
                SsF[r0 * SSP + c]           = v0;
                SsF[r0 * SSP + c + 1]       = v1;
                SsF[(r0 + 8) * SSP + c]     = v2;
                SsF[(r0 + 8) * SSP + c + 1] = v3;
            }
        }
        __syncthreads();

        // ---- softmax on owner rows ----
#pragma unroll
        for (int rr = 0; rr < 8; ++rr) {
            int r = warp * 8 + rr;
            float s0 = SsF[r * SSP + lane];
            float s1 = SsF[r * SSP + lane + 32];
            float mx = fmaxf(s0, s1);
#pragma unroll
            for (int o = 16; o > 0; o >>= 1)
                mx = fmaxf(mx, __shfl_xor_sync(0xFFFFFFFFu, mx, o));
            float m_new = fmaxf(m_i[rr], mx);
            float p0 = __expf(s0 - m_new);
            float p1 = __expf(s1 - m_new);
            SsF[r * SSP + lane]      = p0;
            SsF[r * SSP + lane + 32] = p1;
            float sum = p0 + p1;
#pragma unroll
            for (int o = 16; o > 0; o >>= 1)
                sum += __shfl_xor_sync(0xFFFFFFFFu, sum, o);
            float crr = __expf(m_i[rr] - m_new);
            l_i[rr] = l_i[rr] * crr + sum;
            m_i[rr] = m_new;
            if (lane == 0) corr[r] = crr;
        }
        __syncthreads();

        // ---- convert P -> fp16 hi/lo; scale O accumulators ----
#pragma unroll
        for (int j = 0; j < 8; ++j) {
            int i = tid + j * 256;
            int r = i >> 5;
            int c2 = (i & 31) * 2;
            float p0 = SsF[r * SSP + c2];
            float p1 = SsF[r * SSP + c2 + 1];
            __half h0 = __float2half_rn(p0);
            __half h1 = __float2half_rn(p1);
            *(__half2*)(smx + O_PH + r * PPITCH + c2 * 2) = __halves2half2(h0, h1);
            *(__half2*)(smx + O_PL + r * PPITCH + c2 * 2) =
                __halves2half2(__float2half_rn(p0 - __half2float(h0)),
                               __float2half_rn(p1 - __half2float(h1)));
        }
        {
            float cr0 = corr[wr * 16 + (lane >> 2)];
            float cr1 = corr[wr * 16 + (lane >> 2) + 8];
#pragma unroll
            for (int t = 0; t < 8; ++t) {
                oacc[t][0] *= cr0; oacc[t][1] *= cr0;
                oacc[t][2] *= cr1; oacc[t][3] *= cr1;
            }
        }
        __syncthreads();

        // ---- PV: O += Ph*Vh + Pl*Vh ----
        {
            uint32_t pH = sb + O_PH + (wr * 16 + (lane & 15)) * PPITCH + (lane >> 4) * 16;
            uint32_t pL = pH + (O_PL - O_PH);
            uint32_t vHb = kvb + ATILE + (lane & 15) * APITCH + wc * 128;
#pragma unroll
            for (int s = 0; s < 4; ++s) {
                uint32_t ph4[4], pl4[4];
                ldm_x4(ph4, pH + s * 32);
                ldm_x4(pl4, pL + s * 32);
#pragma unroll
                for (int j = 0; j < 8; ++j) {
                    uint32_t vh2[2];
                    ldm_x2t(vh2, vHb + s * 16 * APITCH + j * 16);
                    mma16816(oacc[j], ph4, vh2[0], vh2[1]);
                    mma16816(oacc[j], pl4, vh2[0], vh2[1]);
                }
            }
        }
    }

    // ---- epilogue ----
    __syncthreads();
    if (lane == 0) {
#pragma unroll
        for (int rr = 0; rr < 8; ++rr)
            linv[warp * 8 + rr] = 1.f / l_i[rr];
    }
    __syncthreads();

    {
        float li0 = linv[wr * 16 + (lane >> 2)];
        float li1 = linv[wr * 16 + (lane >> 2) + 8];
        int orow = qb * 64 + wr * 16 + (lane >> 2);
        int ocol = h * HD + wc * 64 + (lane & 3) * 2;
#pragma unroll
        for (int j = 0; j < 8; ++j) {
            int c = ocol + j * 8;
            float f0 = oacc[j][0] * li0, f1 = oacc[j][1] * li0;
            float f2 = oacc[j][2] * li1, f3 = oacc[j][3] * li1;
            __half h0 = __float2half_rn(f0);
            __half h1 = __float2half_rn(f1);
            __half h2 = __float2half_rn(f2);
            __half h3 = __float2half_rn(f3);
            *(__half2*)&outH[(size_t)orow * HID + c] = __halves2half2(h0, h1);
            *(__half2*)&outL[(size_t)orow * HID + c] =
                __halves2half2(__float2half_rn(f0 - __half2float(h0)),
                               __float2half_rn(f1 - __half2float(h1)));
            *(__half2*)&outH[(size_t)(orow + 8) * HID + c] = __halves2half2(h2, h3);
            *(__half2*)&outL[(size_t)(orow + 8) * HID + c] =
                __halves2half2(__float2half_rn(f2 - __half2float(h2)),
                               __float2half_rn(f3 - __half2float(h3)));
        }
    }
}

// ---------------------------------------------------------------------------
// kernel_launch
// ---------------------------------------------------------------------------
extern "C" void kernel_launch(void* const* d_in, const int* in_sizes, int n_in,
                              void* d_out, int out_size)
{
    const float* hs    = (const float*)d_in[0];
    const int*   pos   = (const int*)d_in[1];
    const float* w_qkv = (const float*)d_in[2];
    const float* w_o   = (const float*)d_in[3];
    float* out = (float*)d_out;

    float* qkv; cudaGetSymbolAddress((void**)&qkv, g_qkv);
    __half *Ah, *Al, *Bh, *Bh2, *Qh, *Ql, *Kh, *Vh;
    cudaGetSymbolAddress((void**)&Ah, g_Ah);
    cudaGetSymbolAddress((void**)&Al, g_Al);
    cudaGetSymbolAddress((void**)&Bh, g_Bh);
    cudaGetSymbolAddress((void**)&Bh2, g_Bh2);
    cudaGetSymbolAddress((void**)&Qh, g_Qh);
    cudaGetSymbolAddress((void**)&Ql, g_Ql);
    cudaGetSymbolAddress((void**)&Kh, g_Kh);
    cudaGetSymbolAddress((void**)&Vh, g_Vh);

    cudaFuncSetAttribute(gemm_mma_kernel,
                         cudaFuncAttributeMaxDynamicSharedMemorySize, GEMM_SMEM);
    cudaFuncSetAttribute(flash_mma_kernel,
                         cudaFuncAttributeMaxDynamicSharedMemorySize, FL_SMEM);

    // 1) split hs ; transpose both weight matrices
    split_kernel<<<(SEQ * HID / 4 + 255) / 256, 256>>>(hs, Ah, Al, SEQ * HID / 4);
    transT_kernel<<<dim3(QKVN / 32, HID / 32), dim3(32, 8)>>>(w_qkv, Bh, HID, QKVN);
    transT_kernel<<<dim3(HID / 32, HID / 32), dim3(32, 8)>>>(w_o, Bh2, HID, HID);

    // 2) QKV projection (tensor cores, fp16 2-term, 2 CTAs/SM)
    gemm_mma_kernel<<<dim3(QKVN / 128, SEQ / 128), 256, GEMM_SMEM>>>(
        Ah, Al, Bh, qkv, HID, QKVN);

    // 3) RoPE + split into fp16 Q(hi/lo)/K/V [h][s][d]
    {
        int total = SEQ * (NH + 2 * NKV) * (HD / 2);
        rope_split_kernel<<<(total + 255) / 256, 256>>>(qkv, pos, Qh, Ql, Kh, Vh);
    }

    // 4) Tensor-core flash attention -> fp16 hi/lo directly into Ah/Al
    flash_mma_kernel<<<dim3(SEQ / 64, NH), 256, FL_SMEM>>>(
        Qh, Ql, Kh, Vh, Ah, Al);

    // 5) Output projection (tensor cores, fp16 2-term, 2 CTAs/SM)
    gemm_mma_kernel<<<dim3(HID / 128, SEQ / 128), 256, GEMM_SMEM>>>(
        Ah, Al, Bh2, out, HID, HID);
}

// round 13
// speedup vs baseline: 1.2121x; 1.0395x over previous
#include <cuda_runtime.h>
#include <cuda_fp16.h>
#include <stdint.h>
#include <math.h>

#define SEQ   2048
#define HID   4096
#define NH    32
#define NKV   8
#define HD    128
#define GRP   (NH / NKV)             // 4
#define QKVN  ((NH + 2 * NKV) * HD)  // 6144

// ---------------------------------------------------------------------------
// Scratch (device globals; no allocations allowed)
// ---------------------------------------------------------------------------
__device__ float g_qkv[SEQ * QKVN];        // QKV output, fp32
__device__ __half g_Ah[SEQ * HID];         // GEMM A hi (hs / attn-out)
__device__ __half g_Al[SEQ * HID];         // GEMM A lo
__device__ __half g_Bh[QKVN * HID];        // w_qkv^T fp16
__device__ __half g_Bh2[HID * HID];        // w_o^T fp16
__device__ __half g_Qh[NH * SEQ * HD];     // roped Q hi  [h][s][d]
__device__ __half g_Ql[NH * SEQ * HD];     // roped Q lo
__device__ __half g_Kh[NKV * SEQ * HD];    // roped K     [h][s][d]
__device__ __half g_Vh[NKV * SEQ * HD];    // V           [h][s][d]

// ---------------------------------------------------------------------------
// PTX helpers (portable: no 'a'-suffix features)
// ---------------------------------------------------------------------------
__device__ __forceinline__ uint32_t s2u(const void* p) {
    uint32_t a;
    asm("{ .reg .u64 t; cvta.to.shared.u64 t, %1; cvt.u32.u64 %0, t; }"
        : "=r"(a) : "l"(p));
    return a;
}

__device__ __forceinline__ void cpa16(uint32_t s, const void* g) {
    asm volatile("cp.async.cg.shared.global [%0], [%1], 16;" :: "r"(s), "l"(g));
}
__device__ __forceinline__ void cpa_commit() {
    asm volatile("cp.async.commit_group;" ::: "memory");
}
template <int N>
__device__ __forceinline__ void cpa_wait() {
    asm volatile("cp.async.wait_group %0;" :: "n"(N) : "memory");
}

__device__ __forceinline__ void ldm_x4(uint32_t* r, uint32_t addr) {
    asm volatile("ldmatrix.sync.aligned.m8n8.x4.shared.b16 {%0,%1,%2,%3}, [%4];"
                 : "=r"(r[0]), "=r"(r[1]), "=r"(r[2]), "=r"(r[3]) : "r"(addr));
}
__device__ __forceinline__ void ldm_x2(uint32_t* r, uint32_t addr) {
    asm volatile("ldmatrix.sync.aligned.m8n8.x2.shared.b16 {%0,%1}, [%2];"
                 : "=r"(r[0]), "=r"(r[1]) : "r"(addr));
}
__device__ __forceinline__ void ldm_x2t(uint32_t* r, uint32_t addr) {
    asm volatile("ldmatrix.sync.aligned.m8n8.x2.trans.shared.b16 {%0,%1}, [%2];"
                 : "=r"(r[0]), "=r"(r[1]) : "r"(addr));
}

// fp16 inputs, fp32 accumulate
__device__ __forceinline__ void mma16816(float* c, const uint32_t* a,
                                         uint32_t b0, uint32_t b1) {
    asm volatile(
        "mma.sync.aligned.m16n8k16.row.col.f32.f16.f16.f32 "
        "{%0,%1,%2,%3}, {%4,%5,%6,%7}, {%8,%9}, {%0,%1,%2,%3};"
        : "+f"(c[0]), "+f"(c[1]), "+f"(c[2]), "+f"(c[3])
        : "r"(a[0]), "r"(a[1]), "r"(a[2]), "r"(a[3]), "r"(b0), "r"(b1));
}

// ---------------------------------------------------------------------------
// Split fp32 -> fp16 hi + lo (elementwise, float4)
// ---------------------------------------------------------------------------
__global__ void split_kernel(const float* __restrict__ in,
                             __half* __restrict__ hi,
                             __half* __restrict__ lo, int n4)
{
    int i = blockIdx.x * blockDim.x + threadIdx.x;
    if (i >= n4) return;
    float4 v = ((const float4*)in)[i];
    __half h0 = __float2half_rn(v.x);
    __half h1 = __float2half_rn(v.y);
    __half h2 = __float2half_rn(v.z);
    __half h3 = __float2half_rn(v.w);
    __half l0 = __float2half_rn(v.x - __half2float(h0));
    __half l1 = __float2half_rn(v.y - __half2float(h1));
    __half l2 = __float2half_rn(v.z - __half2float(h2));
    __half l3 = __float2half_rn(v.w - __half2float(h3));
    __half2* hp = (__half2*)hi;
    __half2* lp = (__half2*)lo;
    hp[2 * i]     = __halves2half2(h0, h1);
    hp[2 * i + 1] = __halves2half2(h2, h3);
    lp[2 * i]     = __halves2half2(l0, l1);
    lp[2 * i + 1] = __halves2half2(l2, l3);
}

// ---------------------------------------------------------------------------
// Transpose + fp16 round (hi only): fp32 [K,N] row-major -> fp16 [N,K]
// ---------------------------------------------------------------------------
__global__ void transT_kernel(const float* __restrict__ in,
                              __half* __restrict__ hi, int K, int N)
{
    __shared__ float t[32][33];
    int n0 = blockIdx.x * 32, k0 = blockIdx.y * 32;
    int tx = threadIdx.x, ty = threadIdx.y;   // 32 x 8
#pragma unroll
    for (int j = 0; j < 4; j++)
        t[ty + 8 * j][tx] = in[(size_t)(k0 + ty + 8 * j) * N + n0 + tx];
    __syncthreads();
#pragma unroll
    for (int j = 0; j < 4; j++) {
        float a = t[tx][ty + 8 * j];
        hi[(size_t)(n0 + ty + 8 * j) * K + k0 + tx] = __float2half_rn(a);
    }
}

// ---------------------------------------------------------------------------
// mma.sync GEMM, fp16 2-term: C = Ah*Bh + Al*Bh.
// CTA 128x128, KC=64, 2-stage cp.async pipeline, 2 CTAs/SM. (round-11 proven)
// ---------------------------------------------------------------------------
#define KC      64
#define PITCH_B 144
#define TILE_SB (128 * PITCH_B)
#define STAGE_B (3 * TILE_SB)            // 55296
#define GEMM_SMEM (2 * STAGE_B)          // 110592 -> 2 CTAs/SM

__global__ __launch_bounds__(256, 2)
void gemm_mma_kernel(const __half* __restrict__ Ah,
                     const __half* __restrict__ Al,
                     const __half* __restrict__ Bh,
                     float* __restrict__ C, int K, int Nc)
{
    extern __shared__ char smc[];
    const uint32_t sbase = s2u(smc);

    const int tid  = threadIdx.x;
    const int lane = tid & 31;
    const int warp = tid >> 5;
    const int wm = warp >> 2;            // 0..1 (64-row halves)
    const int wn = warp & 3;             // 0..3 (32-col quarters)
    const int bm = blockIdx.y, bn = blockIdx.x;
    const int nchunk = K / KC;

    const __half* gsrc[3] = {Ah, Al, Bh};
    const int row0[3] = {bm * 128, bm * 128, bn * 128};

    auto load_stage = [&](int c, int s) {
        uint32_t stg = sbase + s * STAGE_B;
        int kt = c * KC;
#pragma unroll
        for (int j = 0; j < 12; ++j) {
            int idx  = tid + j * 256;
            int tsel = idx >> 10;
            int w    = idx & 1023;
            int r    = w >> 3;
            int ck   = w & 7;
            cpa16(stg + tsel * TILE_SB + r * PITCH_B + ck * 16,
                  gsrc[tsel] + (size_t)(row0[tsel] + r) * K + kt + ck * 8);
        }
    };

    float acc[4][4][4];
#pragma unroll
    for (int i = 0; i < 4; i++)
#pragma unroll
        for (int j = 0; j < 4; j++)
#pragma unroll
            for (int q = 0; q < 4; q++) acc[i][j][q] = 0.f;

    load_stage(0, 0);
    cpa_commit();

    for (int c = 0; c < nchunk; ++c) {
        if (c + 1 < nchunk) {
            load_stage(c + 1, (c + 1) & 1);
            cpa_commit();
            cpa_wait<1>();
        } else {
            cpa_wait<0>();
        }
        __syncthreads();

        uint32_t stg = sbase + (c & 1) * STAGE_B;
        uint32_t aBaseH = stg + (wm * 64 + (lane & 15)) * PITCH_B + (lane >> 4) * 16;
        uint32_t aBaseL = aBaseH + TILE_SB;
        uint32_t bBase  = stg + 2 * TILE_SB +
                          (wn * 32 + (lane & 7)) * PITCH_B + ((lane >> 3) & 1) * 16;

#pragma unroll
        for (int s = 0; s < 4; ++s) {
            uint32_t ah[4][4], al[4][4], bh[4][2];
#pragma unroll
            for (int i = 0; i < 4; ++i) {
                ldm_x4(ah[i], aBaseH + i * 16 * PITCH_B + s * 32);
                ldm_x4(al[i], aBaseL + i * 16 * PITCH_B + s * 32);
            }
#pragma unroll
            for (int j = 0; j < 4; ++j)
                ldm_x2(bh[j], bBase + j * 8 * PITCH_B + s * 32);
#pragma unroll
            for (int i = 0; i < 4; ++i)
#pragma unroll
                for (int j = 0; j < 4; ++j) {
                    mma16816(acc[i][j], ah[i], bh[j][0], bh[j][1]);
                    mma16816(acc[i][j], al[i], bh[j][0], bh[j][1]);
                }
        }
        __syncthreads();
    }

    const int rbase = bm * 128 + wm * 64 + (lane >> 2);
    const int cbase = bn * 128 + wn * 32 + (lane & 3) * 2;
#pragma unroll
    for (int i = 0; i < 4; ++i) {
#pragma unroll
        for (int j = 0; j < 4; ++j) {
            int r = rbase + i * 16;
            int col = cbase + j * 8;
            *(float2*)&C[(size_t)r * Nc + col] =
                make_float2(acc[i][j][0], acc[i][j][1]);
            *(float2*)&C[(size_t)(r + 8) * Nc + col] =
                make_float2(acc[i][j][2], acc[i][j][3]);
        }
    }
}

// ---------------------------------------------------------------------------
// RoPE + fp16 split: fp32 qkv -> Qh/Ql (scaled), Kh, Vh in [h][s][d].
// ---------------------------------------------------------------------------
__global__ void rope_split_kernel(const float* __restrict__ qkv,
                                  const int* __restrict__ positions,
                                  __half* __restrict__ Qh, __half* __restrict__ Ql,
                                  __half* __restrict__ Kh, __half* __restrict__ Vh)
{
    int idx = blockIdx.x * blockDim.x + threadIdx.x;
    const int NHTOT = NH + 2 * NKV;  // 48
    const int TOTAL = SEQ * NHTOT * (HD / 2);
    if (idx >= TOTAL) return;

    int d = idx & 63;
    int h = (idx >> 6) % NHTOT;
    int s = idx / (NHTOT * 64);

    const float* base = qkv + (size_t)s * QKVN + h * HD;
    float x1 = base[d];
    float x2 = base[d + 64];
    float y1 = x1, y2 = x2;

    if (h < NH + NKV) {
        float pos = (float)positions[s];
        float inv = powf(10000.0f, -(2.0f * (float)d) / (float)HD);
        float ang = pos * inv;
        float c, sn;
        sincosf(ang, &sn, &c);
        y1 = x1 * c - x2 * sn;
        y2 = x2 * c + x1 * sn;
    }

    if (h < NH) {
        const float scale = 0.088388347648318447f;  // 1/sqrt(128)
        y1 *= scale; y2 *= scale;
        size_t off = ((size_t)h * SEQ + s) * HD + d;
        __half h1 = __float2half_rn(y1);
        __half h2 = __float2half_rn(y2);
        Qh[off]      = h1;
        Qh[off + 64] = h2;
        Ql[off]      = __float2half_rn(y1 - __half2float(h1));
        Ql[off + 64] = __float2half_rn(y2 - __half2float(h2));
    } else if (h < NH + NKV) {
        size_t off = ((size_t)(h - NH) * SEQ + s) * HD + d;
        Kh[off]      = __float2half_rn(y1);
        Kh[off + 64] = __float2half_rn(y2);
    } else {
        size_t off = ((size_t)(h - NH - NKV) * SEQ + s) * HD + d;
        Vh[off]      = __float2half_rn(y1);
        Vh[off + 64] = __float2half_rn(y2);
    }
}

// ---------------------------------------------------------------------------
// Tensor-core flash attention (fp16 2-term), causal, GQA. Br=Bc=64, 256 thr.
// Single-buffered K/V, 103.5 KB smem -> 2 CTAs/SM.
// ---------------------------------------------------------------------------
#define APITCH 272
#define PPITCH 144
#define SSP    68
#define ATILE  (64 * APITCH)            // 17408
#define O_QH   0
#define O_QL   (O_QH + ATILE)           // 17408
#define O_KV   (O_QL + ATILE)           // 34816 (K tile, V tile)
#define O_SS   (O_KV + 2 * ATILE)       // 69632
#define O_PH   (O_SS + 64 * SSP * 4)    // 87040
#define O_PL   (O_PH + 64 * PPITCH)     // 96256
#define O_CORR (O_PL + 64 * PPITCH)     // 105472
#define O_LINV (O_CORR + 256)           // 105728
#define FL_SMEM (O_LINV + 256)          // 105984 -> 2 CTAs/SM

__global__ __launch_bounds__(256, 2)
void flash_mma_kernel(const __half* __restrict__ Qh, const __half* __restrict__ Ql,
                      const __half* __restrict__ Kh, const __half* __restrict__ Vh,
                      __half* __restrict__ outH, __half* __restrict__ outL)
{
    extern __shared__ char smx[];
    const uint32_t sb = s2u(smx);
    float* SsF  = (float*)(smx + O_SS);
    float* corr = (float*)(smx + O_CORR);
    float* linv = (float*)(smx + O_LINV);

    const int qb = (int)gridDim.x - 1 - (int)blockIdx.x;  // longest first
    const int h  = blockIdx.y;
    const int kvh = h / GRP;

    const int tid  = threadIdx.x;
    const int warp = tid >> 5;
    const int lane = tid & 31;
    const int wr = warp & 3;
    const int wc = warp >> 2;

    const __half* kH = Kh + (size_t)kvh * SEQ * HD;
    const __half* vH = Vh + (size_t)kvh * SEQ * HD;
    const __half* kvsrc[2] = {kH, vH};

    auto load_kv = [&](int kb) {
#pragma unroll
        for (int j = 0; j < 8; ++j) {
            int idx = tid + j * 256;
            int tsel = idx >> 10;
            int w = idx & 1023;
            int r = w >> 4, ck = w & 15;
            cpa16(sb + O_KV + tsel * ATILE + r * APITCH + ck * 16,
                  kvsrc[tsel] + ((size_t)(kb * 64 + r)) * HD + ck * 8);
        }
    };

    // --- prologue: Q tiles ---
    {
        const __half* qH = Qh + ((size_t)h * SEQ + qb * 64) * HD;
        const __half* qL = Ql + ((size_t)h * SEQ + qb * 64) * HD;
#pragma unroll
        for (int j = 0; j < 8; ++j) {
            int idx = tid + j * 256;
            int tsel = idx >> 10;
            int w = idx & 1023;
            int r = w >> 4, ck = w & 15;
            cpa16(sb + (tsel ? O_QL : O_QH) + r * APITCH + ck * 16,
                  (tsel ? qL : qH) + (size_t)r * HD + ck * 8);
        }
        cpa_commit();
    }

    float m_i[8], l_i[8], oacc[8][4];
#pragma unroll
    for (int r = 0; r < 8; ++r) { m_i[r] = -1e30f; l_i[r] = 0.f; }
#pragma unroll
    for (int t = 0; t < 8; ++t)
#pragma unroll
        for (int q = 0; q < 4; ++q) oacc[t][q] = 0.f;

    for (int kb = 0; kb <= qb; ++kb) {
        __syncthreads();   // all reads of K/V from previous iter complete
        load_kv(kb);
        cpa_commit();
        cpa_wait<0>();     // Q (first iter) + KV resident
        __syncthreads();

        // ---- QK: S = Qh*Kh + Ql*Kh ----
        float sf[4][4];
#pragma unroll
        for (int j = 0; j < 4; ++j)
#pragma unroll
            for (int q = 0; q < 4; ++q) sf[j][q] = 0.f;

        uint32_t aH = sb + O_QH + (wr * 16 + (lane & 15)) * APITCH + (lane >> 4) * 16;
        uint32_t aL = aH + ATILE;
        uint32_t bH = sb + O_KV + (wc * 32 + (lane & 7)) * APITCH + ((lane >> 3) & 1) * 16;
#pragma unroll
        for (int s = 0; s < 8; ++s) {
            uint32_t qh4[4], ql4[4];
            ldm_x4(qh4, aH + s * 32);
            ldm_x4(ql4, aL + s * 32);
#pragma unroll
            for (int j = 0; j < 4; ++j) {
                uint32_t kh2[2];
                ldm_x2(kh2, bH + j * 8 * APITCH + s * 32);
                mma16816(sf[j], qh4, kh2[0], kh2[1]);
                mma16816(sf[j], ql4, kh2[0], kh2[1]);
            }
        }

        // store S to smem with causal mask
        {
            int r0 = wr * 16 + (lane >> 2);
            int c0 = wc * 32 + (lane & 3) * 2;
            bool diag = (kb == qb);
#pragma unroll
            for (int j = 0; j < 4; ++j) {
                int c = c0 + j * 8;
                float v0 = sf[j][0], v1 = sf[j][1], v2 = sf[j][2], v3 = sf[j][3];
                if (diag) {
                    if (c > r0)         v0 = -1e30f;
                    if (c + 1 > r0)     v1 = -1e30f;
                    if (c > r0 + 8)     v2 = -1e30f;
                    if (c + 1 > r0 + 8) v3 = -1e30f;
                }
                SsF[r0 * SSP + c]           = v0;
                SsF[r0 * SSP + c + 1]       = v1;
                SsF[(r0 + 8) * SSP + c]     = v2;
                SsF[(r0 + 8) * SSP + c + 1] = v3;
            }
        }
        __syncthreads();

        // ---- softmax on owner rows ----
#pragma unroll
        for (int rr = 0; rr < 8; ++rr) {
            int r = warp * 8 + rr;
            float s0 = SsF[r * SSP + lane];
            float s1 = SsF[r * SSP + lane + 32];
            float mx = fmaxf(s0, s1);
#pragma unroll
            for (int o = 16; o > 0; o >>= 1)
                mx = fmaxf(mx, __shfl_xor_sync(0xFFFFFFFFu, mx, o));
            float m_new = fmaxf(m_i[rr], mx);
            float p0 = __expf(s0 - m_new);
            float p1 = __expf(s1 - m_new);
            SsF[r * SSP + lane]      = p0;
            SsF[r * SSP + lane + 32] = p1;
            float sum = p0 + p1;
#pragma unroll
            for (int o = 16; o > 0; o >>= 1)
                sum += __shfl_xor_sync(0xFFFFFFFFu, sum, o);
            float crr = __expf(m_i[rr] - m_new);
            l_i[rr] = l_i[rr] * crr + sum;
            m_i[rr] = m_new;
            if (lane == 0) corr[r] = crr;
        }
        __syncthreads();

        // ---- convert P -> fp16 hi/lo; scale O accumulators ----
#pragma unroll
        for (int j = 0; j < 8; ++j) {
            int i = tid + j * 256;
            int r = i >> 5;
            int c2 = (i & 31) * 2;
            float p0 = SsF[r * SSP + c2];
            float p1 = SsF[r * SSP + c2 + 1];
            __half h0 = __float2half_rn(p0);
            __half h1 = __float2half_rn(p1);
            *(__half2*)(smx + O_PH + r * PPITCH + c2 * 2) = __halves2half2(h0, h1);
            *(__half2*)(smx + O_PL + r * PPITCH + c2 * 2) =
                __halves2half2(__float2half_rn(p0 - __half2float(h0)),
                               __float2half_rn(p1 - __half2float(h1)));
        }
        {
            float cr0 = corr[wr * 16 + (lane >> 2)];
            float cr1 = corr[wr * 16 + (lane >> 2) + 8];
#pragma unroll
            for (int t = 0; t < 8; ++t) {
                oacc[t][0] *= cr0; oacc[t][1] *= cr0;
                oacc[t][2] *= cr1; oacc[t][3] *= cr1;
            }
        }
        __syncthreads();

        // ---- PV: O += Ph*Vh + Pl*Vh ----
        {
            uint32_t pH = sb + O_PH + (wr * 16 + (lane & 15)) * PPITCH + (lane >> 4) * 16;
            uint32_t pL = pH + (O_PL - O_PH);
            uint32_t vHb = sb + O_KV + ATILE + (lane & 15) * APITCH + wc * 128;
#pragma unroll
            for (int s = 0; s < 4; ++s) {
                uint32_t ph4[4], pl4[4];
                ldm_x4(ph4, pH + s * 32);
                ldm_x4(pl4, pL + s * 32);
#pragma unroll
                for (int j = 0; j < 8; ++j) {
                    uint32_t vh2[2];
                    ldm_x2t(vh2, vHb + s * 16 * APITCH + j * 16);
                    mma16816(oacc[j], ph4, vh2[0], vh2[1]);
                    mma16816(oacc[j], pl4, vh2[0], vh2[1]);
                }
            }
        }
    }

    // ---- epilogue ----
    __syncthreads();
    if (lane == 0) {
#pragma unroll
        for (int rr = 0; rr < 8; ++rr)
            linv[warp * 8 + rr] = 1.f / l_i[rr];
    }
    __syncthreads();

    {
        float li0 = linv[wr * 16 + (lane >> 2)];
        float li1 = linv[wr * 16 + (lane >> 2) + 8];
        int orow = qb * 64 + wr * 16 + (lane >> 2);
        int ocol = h * HD + wc * 64 + (lane & 3) * 2;
#pragma unroll
        for (int j = 0; j < 8; ++j) {
            int c = ocol + j * 8;
            float f0 = oacc[j][0] * li0, f1 = oacc[j][1] * li0;
            float f2 = oacc[j][2] * li1, f3 = oacc[j][3] * li1;
            __half h0 = __float2half_rn(f0);
            __half h1 = __float2half_rn(f1);
            __half h2 = __float2half_rn(f2);
            __half h3 = __float2half_rn(f3);
            *(__half2*)&outH[(size_t)orow * HID + c] = __halves2half2(h0, h1);
            *(__half2*)&outL[(size_t)orow * HID + c] =
                __halves2half2(__float2half_rn(f0 - __half2float(h0)),
                               __float2half_rn(f1 - __half2float(h1)));
            *(__half2*)&outH[(size_t)(orow + 8) * HID + c] = __halves2half2(h2, h3);
            *(__half2*)&outL[(size_t)(orow + 8) * HID + c] =
                __halves2half2(__float2half_rn(f2 - __half2float(h2)),
                               __float2half_rn(f3 - __half2float(h3)));
        }
    }
}

// ---------------------------------------------------------------------------
// kernel_launch
// ---------------------------------------------------------------------------
extern "C" void kernel_launch(void* const* d_in, const int* in_sizes, int n_in,
                              void* d_out, int out_size)
{
    const float* hs    = (const float*)d_in[0];
    const int*   pos   = (const int*)d_in[1];
    const float* w_qkv = (const float*)d_in[2];
    const float* w_o   = (const float*)d_in[3];
    float* out = (float*)d_out;

    float* qkv; cudaGetSymbolAddress((void**)&qkv, g_qkv);
    __half *Ah, *Al, *Bh, *Bh2, *Qh, *Ql, *Kh, *Vh;
    cudaGetSymbolAddress((void**)&Ah, g_Ah);
    cudaGetSymbolAddress((void**)&Al, g_Al);
    cudaGetSymbolAddress((void**)&Bh, g_Bh);
    cudaGetSymbolAddress((void**)&Bh2, g_Bh2);
    cudaGetSymbolAddress((void**)&Qh, g_Qh);
    cudaGetSymbolAddress((void**)&Ql, g_Ql);
    cudaGetSymbolAddress((void**)&Kh, g_Kh);
    cudaGetSymbolAddress((void**)&Vh, g_Vh);

    cudaFuncSetAttribute(gemm_mma_kernel,
                         cudaFuncAttributeMaxDynamicSharedMemorySize, GEMM_SMEM);
    cudaFuncSetAttribute(flash_mma_kernel,
                         cudaFuncAttributeMaxDynamicSharedMemorySize, FL_SMEM);

    // 1) split hs ; transpose both weight matrices
    split_kernel<<<(SEQ * HID / 4 + 255) / 256, 256>>>(hs, Ah, Al, SEQ * HID / 4);
    transT_kernel<<<dim3(QKVN / 32, HID / 32), dim3(32, 8)>>>(w_qkv, Bh, HID, QKVN);
    transT_kernel<<<dim3(HID / 32, HID / 32), dim3(32, 8)>>>(w_o, Bh2, HID, HID);

    // 2) QKV projection (tensor cores, fp16 2-term, 2 CTAs/SM)
    gemm_mma_kernel<<<dim3(QKVN / 128, SEQ / 128), 256, GEMM_SMEM>>>(
        Ah, Al, Bh, qkv, HID, QKVN);

    // 3) RoPE + split into fp16 Q(hi/lo)/K/V [h][s][d]
    {
        int total = SEQ * (NH + 2 * NKV) * (HD / 2);
        rope_split_kernel<<<(total + 255) / 256, 256>>>(qkv, pos, Qh, Ql, Kh, Vh);
    }

    // 4) Tensor-core flash attention (2 CTAs/SM) -> fp16 hi/lo into Ah/Al
    flash_mma_kernel<<<dim3(SEQ / 64, NH), 256, FL_SMEM>>>(
        Qh, Ql, Kh, Vh, Ah, Al);

    // 5) Output projection (tensor cores, fp16 2-term, 2 CTAs/SM)
    gemm_mma_kernel<<<dim3(HID / 128, SEQ / 128), 256, GEMM_SMEM>>>(
        Ah, Al, Bh2, out, HID, HID);
}

// round 15
// speedup vs baseline: 1.7636x; 1.4550x over previous
#include <cuda_runtime.h>
#include <cuda_fp16.h>
#include <stdint.h>
#include <math.h>

#define SEQ   2048
#define HID   4096
#define NH    32
#define NKV   8
#define HD    128
#define GRP   (NH / NKV)             // 4
#define QKVN  ((NH + 2 * NKV) * HD)  // 6144

// ---------------------------------------------------------------------------
// Scratch (device globals; no allocations allowed)
// ---------------------------------------------------------------------------
__device__ float g_qkv[SEQ * QKVN];        // QKV output, fp32
__device__ __half g_Ah[SEQ * HID];         // GEMM A (hs cast / attn-out)
__device__ __half g_Bh[QKVN * HID];        // w_qkv^T fp16
__device__ __half g_Bh2[HID * HID];        // w_o^T fp16
__device__ __half g_Qh[NH * SEQ * HD];     // roped Q hi  [h][s][d]
__device__ __half g_Ql[NH * SEQ * HD];     // roped Q lo
__device__ __half g_Kh[NKV * SEQ * HD];    // roped K     [h][s][d]
__device__ __half g_Vh[NKV * SEQ * HD];    // V           [h][s][d]

// ---------------------------------------------------------------------------
// PTX helpers (portable: no 'a'-suffix features)
// ---------------------------------------------------------------------------
__device__ __forceinline__ uint32_t s2u(const void* p) {
    uint32_t a;
    asm("{ .reg .u64 t; cvta.to.shared.u64 t, %1; cvt.u32.u64 %0, t; }"
        : "=r"(a) : "l"(p));
    return a;
}

__device__ __forceinline__ void cpa16(uint32_t s, const void* g) {
    asm volatile("cp.async.cg.shared.global [%0], [%1], 16;" :: "r"(s), "l"(g));
}
__device__ __forceinline__ void cpa_commit() {
    asm volatile("cp.async.commit_group;" ::: "memory");
}
template <int N>
__device__ __forceinline__ void cpa_wait() {
    asm volatile("cp.async.wait_group %0;" :: "n"(N) : "memory");
}

__device__ __forceinline__ void ldm_x4(uint32_t* r, uint32_t addr) {
    asm volatile("ldmatrix.sync.aligned.m8n8.x4.shared.b16 {%0,%1,%2,%3}, [%4];"
                 : "=r"(r[0]), "=r"(r[1]), "=r"(r[2]), "=r"(r[3]) : "r"(addr));
}
__device__ __forceinline__ void ldm_x2(uint32_t* r, uint32_t addr) {
    asm volatile("ldmatrix.sync.aligned.m8n8.x2.shared.b16 {%0,%1}, [%2];"
                 : "=r"(r[0]), "=r"(r[1]) : "r"(addr));
}
__device__ __forceinline__ void ldm_x2t(uint32_t* r, uint32_t addr) {
    asm volatile("ldmatrix.sync.aligned.m8n8.x2.trans.shared.b16 {%0,%1}, [%2];"
                 : "=r"(r[0]), "=r"(r[1]) : "r"(addr));
}

// fp16 inputs, fp32 accumulate
__device__ __forceinline__ void mma16816(float* c, const uint32_t* a,
                                         uint32_t b0, uint32_t b1) {
    asm volatile(
        "mma.sync.aligned.m16n8k16.row.col.f32.f16.f16.f32 "
        "{%0,%1,%2,%3}, {%4,%5,%6,%7}, {%8,%9}, {%0,%1,%2,%3};"
        : "+f"(c[0]), "+f"(c[1]), "+f"(c[2]), "+f"(c[3])
        : "r"(a[0]), "r"(a[1]), "r"(a[2]), "r"(a[3]), "r"(b0), "r"(b1));
}

// ---------------------------------------------------------------------------
// Cast fp32 -> fp16 (elementwise, float4)
// ---------------------------------------------------------------------------
__global__ void cast_kernel(const float* __restrict__ in,
                            __half* __restrict__ hi, int n4)
{
    int i = blockIdx.x * blockDim.x + threadIdx.x;
    if (i >= n4) return;
    float4 v = ((const float4*)in)[i];
    __half2* hp = (__half2*)hi;
    hp[2 * i]     = __halves2half2(__float2half_rn(v.x), __float2half_rn(v.y));
    hp[2 * i + 1] = __halves2half2(__float2half_rn(v.z), __float2half_rn(v.w));
}

// ---------------------------------------------------------------------------
// Transpose + fp16 round: fp32 [K,N] row-major -> fp16 [N,K]
// ---------------------------------------------------------------------------
__global__ void transT_kernel(const float* __restrict__ in,
                              __half* __restrict__ hi, int K, int N)
{
    __shared__ float t[32][33];
    int n0 = blockIdx.x * 32, k0 = blockIdx.y * 32;
    int tx = threadIdx.x, ty = threadIdx.y;   // 32 x 8
#pragma unroll
    for (int j = 0; j < 4; j++)
        t[ty + 8 * j][tx] = in[(size_t)(k0 + ty + 8 * j) * N + n0 + tx];
    __syncthreads();
#pragma unroll
    for (int j = 0; j < 4; j++) {
        float a = t[tx][ty + 8 * j];
        hi[(size_t)(n0 + ty + 8 * j) * K + k0 + tx] = __float2half_rn(a);
    }
}

// ---------------------------------------------------------------------------
// mma.sync GEMM, pure fp16: C = Ah*Bh.
// CTA 128x128, KC=64, 2-stage cp.async pipeline, 2 CTAs/SM.
// ---------------------------------------------------------------------------
#define KC      64
#define PITCH_B 144
#define TILE_SB (128 * PITCH_B)          // 18432
#define STAGE_B (2 * TILE_SB)            // 36864 (A, B)
#define GEMM_SMEM (2 * STAGE_B)          // 73728 -> 2 CTAs/SM

__global__ __launch_bounds__(256, 2)
void gemm_mma_kernel(const __half* __restrict__ Ah,
                     const __half* __restrict__ Bh,
                     float* __restrict__ C, int K, int Nc)
{
    extern __shared__ char smc[];
    const uint32_t sbase = s2u(smc);

    const int tid  = threadIdx.x;
    const int lane = tid & 31;
    const int warp = tid >> 5;
    const int wm = warp >> 2;            // 0..1 (64-row halves)
    const int wn = warp & 3;             // 0..3 (32-col quarters)
    const int bm = blockIdx.y, bn = blockIdx.x;
    const int nchunk = K / KC;

    const __half* gsrc[2] = {Ah, Bh};
    const int row0[2] = {bm * 128, bn * 128};

    auto load_stage = [&](int c, int s) {
        uint32_t stg = sbase + s * STAGE_B;
        int kt = c * KC;
#pragma unroll
        for (int j = 0; j < 8; ++j) {           // 2 tiles * 1024 chunks
            int idx  = tid + j * 256;
            int tsel = idx >> 10;
            int w    = idx & 1023;
            int r    = w >> 3;
            int ck   = w & 7;
            cpa16(stg + tsel * TILE_SB + r * PITCH_B + ck * 16,
                  gsrc[tsel] + (size_t)(row0[tsel] + r) * K + kt + ck * 8);
        }
    };

    float acc[4][4][4];
#pragma unroll
    for (int i = 0; i < 4; i++)
#pragma unroll
        for (int j = 0; j < 4; j++)
#pragma unroll
            for (int q = 0; q < 4; q++) acc[i][j][q] = 0.f;

    load_stage(0, 0);
    cpa_commit();

    for (int c = 0; c < nchunk; ++c) {
        if (c + 1 < nchunk) {
            load_stage(c + 1, (c + 1) & 1);
            cpa_commit();
            cpa_wait<1>();
        } else {
            cpa_wait<0>();
        }
        __syncthreads();

        uint32_t stg = sbase + (c & 1) * STAGE_B;
        uint32_t aBase = stg + (wm * 64 + (lane & 15)) * PITCH_B + (lane >> 4) * 16;
        uint32_t bBase = stg + TILE_SB +
                         (wn * 32 + (lane & 7)) * PITCH_B + ((lane >> 3) & 1) * 16;

#pragma unroll
        for (int s = 0; s < 4; ++s) {
            uint32_t ah[4][4], bh[4][2];
#pragma unroll
            for (int i = 0; i < 4; ++i)
                ldm_x4(ah[i], aBase + i * 16 * PITCH_B + s * 32);
#pragma unroll
            for (int j = 0; j < 4; ++j)
                ldm_x2(bh[j], bBase + j * 8 * PITCH_B + s * 32);
#pragma unroll
            for (int i = 0; i < 4; ++i)
#pragma unroll
                for (int j = 0; j < 4; ++j)
                    mma16816(acc[i][j], ah[i], bh[j][0], bh[j][1]);
        }
        __syncthreads();
    }

    const int rbase = bm * 128 + wm * 64 + (lane >> 2);
    const int cbase = bn * 128 + wn * 32 + (lane & 3) * 2;
#pragma unroll
    for (int i = 0; i < 4; ++i) {
#pragma unroll
        for (int j = 0; j < 4; ++j) {
            int r = rbase + i * 16;
            int col = cbase + j * 8;
            *(float2*)&C[(size_t)r * Nc + col] =
                make_float2(acc[i][j][0], acc[i][j][1]);
            *(float2*)&C[(size_t)(r + 8) * Nc + col] =
                make_float2(acc[i][j][2], acc[i][j][3]);
        }
    }
}

// ---------------------------------------------------------------------------
// RoPE + fp16 split: fp32 qkv -> Qh/Ql (scaled), Kh, Vh in [h][s][d].
// ---------------------------------------------------------------------------
__global__ void rope_split_kernel(const float* __restrict__ qkv,
                                  const int* __restrict__ positions,
                                  __half* __restrict__ Qh, __half* __restrict__ Ql,
                                  __half* __restrict__ Kh, __half* __restrict__ Vh)
{
    int idx = blockIdx.x * blockDim.x + threadIdx.x;
    const int NHTOT = NH + 2 * NKV;  // 48
    const int TOTAL = SEQ * NHTOT * (HD / 2);
    if (idx >= TOTAL) return;

    int d = idx & 63;
    int h = (idx >> 6) % NHTOT;
    int s = idx / (NHTOT * 64);

    const float* base = qkv + (size_t)s * QKVN + h * HD;
    float x1 = base[d];
    float x2 = base[d + 64];
    float y1 = x1, y2 = x2;

    if (h < NH + NKV) {
        float pos = (float)positions[s];
        float inv = powf(10000.0f, -(2.0f * (float)d) / (float)HD);
        float ang = pos * inv;
        float c, sn;
        sincosf(ang, &sn, &c);
        y1 = x1 * c - x2 * sn;
        y2 = x2 * c + x1 * sn;
    }

    if (h < NH) {
        const float scale = 0.088388347648318447f;  // 1/sqrt(128)
        y1 *= scale; y2 *= scale;
        size_t off = ((size_t)h * SEQ + s) * HD + d;
        __half h1 = __float2half_rn(y1);
        __half h2 = __float2half_rn(y2);
        Qh[off]      = h1;
        Qh[off + 64] = h2;
        Ql[off]      = __float2half_rn(y1 - __half2float(h1));
        Ql[off + 64] = __float2half_rn(y2 - __half2float(h2));
    } else if (h < NH + NKV) {
        size_t off = ((size_t)(h - NH) * SEQ + s) * HD + d;
        Kh[off]      = __float2half_rn(y1);
        Kh[off + 64] = __float2half_rn(y2);
    } else {
        size_t off = ((size_t)(h - NH - NKV) * SEQ + s) * HD + d;
        Vh[off]      = __float2half_rn(y1);
        Vh[off + 64] = __float2half_rn(y2);
    }
}

// ---------------------------------------------------------------------------
// Tensor-core flash attention (fp16 2-term), causal, GQA. Br=Bc=64, 256 thr.
// Single-buffered K/V, 103.5 KB smem -> 2 CTAs/SM. Output fp16 (hi only).
// ---------------------------------------------------------------------------
#define APITCH 272
#define PPITCH 144
#define SSP    68
#define ATILE  (64 * APITCH)            // 17408
#define O_QH   0
#define O_QL   (O_QH + ATILE)           // 17408
#define O_KV   (O_QL + ATILE)           // 34816 (K tile, V tile)
#define O_SS   (O_KV + 2 * ATILE)       // 69632
#define O_PH   (O_SS + 64 * SSP * 4)    // 87040
#define O_PL   (O_PH + 64 * PPITCH)     // 96256
#define O_CORR (O_PL + 64 * PPITCH)     // 105472
#define O_LINV (O_CORR + 256)           // 105728
#define FL_SMEM (O_LINV + 256)          // 105984 -> 2 CTAs/SM

__global__ __launch_bounds__(256, 2)
void flash_mma_kernel(const __half* __restrict__ Qh, const __half* __restrict__ Ql,
                      const __half* __restrict__ Kh, const __half* __restrict__ Vh,
                      __half* __restrict__ outH)
{
    extern __shared__ char smx[];
    const uint32_t sb = s2u(smx);
    float* SsF  = (float*)(smx + O_SS);
    float* corr = (float*)(smx + O_CORR);
    float* linv = (float*)(smx + O_LINV);

    const int qb = (int)gridDim.x - 1 - (int)blockIdx.x;  // longest first
    const int h  = blockIdx.y;
    const int kvh = h / GRP;

    const int tid  = threadIdx.x;
    const int warp = tid >> 5;
    const int lane = tid & 31;
    const int wr = warp & 3;
    const int wc = warp >> 2;

    const __half* kH = Kh + (size_t)kvh * SEQ * HD;
    const __half* vH = Vh + (size_t)kvh * SEQ * HD;
    const __half* kvsrc[2] = {kH, vH};

    auto load_kv = [&](int kb) {
#pragma unroll
        for (int j = 0; j < 8; ++j) {
            int idx = tid + j * 256;
            int tsel = idx >> 10;
            int w = idx & 1023;
            int r = w >> 4, ck = w & 15;
            cpa16(sb + O_KV + tsel * ATILE + r * APITCH + ck * 16,
                  kvsrc[tsel] + ((size_t)(kb * 64 + r)) * HD + ck * 8);
        }
    };

    // --- prologue: Q tiles ---
    {
        const __half* qH = Qh + ((size_t)h * SEQ + qb * 64) * HD;
        const __half* qL = Ql + ((size_t)h * SEQ + qb * 64) * HD;
#pragma unroll
        for (int j = 0; j < 8; ++j) {
            int idx = tid + j * 256;
            int tsel = idx >> 10;
            int w = idx & 1023;
            int r = w >> 4, ck = w & 15;
            cpa16(sb + (tsel ? O_QL : O_QH) + r * APITCH + ck * 16,
                  (tsel ? qL : qH) + (size_t)r * HD + ck * 8);
        }
        cpa_commit();
    }

    float m_i[8], l_i[8], oacc[8][4];
#pragma unroll
    for (int r = 0; r < 8; ++r) { m_i[r] = -1e30f; l_i[r] = 0.f; }
#pragma unroll
    for (int t = 0; t < 8; ++t)
#pragma unroll
        for (int q = 0; q < 4; ++q) oacc[t][q] = 0.f;

    for (int kb = 0; kb <= qb; ++kb) {
        __syncthreads();   // all reads of K/V from previous iter complete
        load_kv(kb);
        cpa_commit();
        cpa_wait<0>();     // Q (first iter) + KV resident
        __syncthreads();

        // ---- QK: S = Qh*Kh + Ql*Kh ----
        float sf[4][4];
#pragma unroll
        for (int j = 0; j < 4; ++j)
#pragma unroll
            for (int q = 0; q < 4; ++q) sf[j][q] = 0.f;

        uint32_t aH = sb + O_QH + (wr * 16 + (lane & 15)) * APITCH + (lane >> 4) * 16;
        uint32_t aL = aH + ATILE;
        uint32_t bH = sb + O_KV + (wc * 32 + (lane & 7)) * APITCH + ((lane >> 3) & 1) * 16;
#pragma unroll
        for (int s = 0; s < 8; ++s) {
            uint32_t qh4[4], ql4[4];
            ldm_x4(qh4, aH + s * 32);
            ldm_x4(ql4, aL + s * 32);
#pragma unroll
            for (int j = 0; j < 4; ++j) {
                uint32_t kh2[2];
                ldm_x2(kh2, bH + j * 8 * APITCH + s * 32);
                mma16816(sf[j], qh4, kh2[0], kh2[1]);
                mma16816(sf[j], ql4, kh2[0], kh2[1]);
            }
        }

        // store S to smem with causal mask
        {
            int r0 = wr * 16 + (lane >> 2);
            int c0 = wc * 32 + (lane & 3) * 2;
            bool diag = (kb == qb);
#pragma unroll
            for (int j = 0; j < 4; ++j) {
                int c = c0 + j * 8;
                float v0 = sf[j][0], v1 = sf[j][1], v2 = sf[j][2], v3 = sf[j][3];
                if (diag) {
                    if (c > r0)         v0 = -1e30f;
                    if (c + 1 > r0)     v1 = -1e30f;
                    if (c > r0 + 8)     v2 = -1e30f;
                    if (c + 1 > r0 + 8) v3 = -1e30f;
                }
                SsF[r0 * SSP + c]           = v0;
                SsF[r0 * SSP + c + 1]       = v1;
                SsF[(r0 + 8) * SSP + c]     = v2;
                SsF[(r0 + 8) * SSP + c + 1] = v3;
            }
        }
        __syncthreads();

        // ---- softmax on owner rows ----
#pragma unroll
        for (int rr = 0; rr < 8; ++rr) {
            int r = warp * 8 + rr;
            float s0 = SsF[r * SSP + lane];
            float s1 = SsF[r * SSP + lane + 32];
            float mx = fmaxf(s0, s1);
#pragma unroll
            for (int o = 16; o > 0; o >>= 1)
                mx = fmaxf(mx, __shfl_xor_sync(0xFFFFFFFFu, mx, o));
            float m_new = fmaxf(m_i[rr], mx);
            float p0 = __expf(s0 - m_new);
            float p1 = __expf(s1 - m_new);
            SsF[r * SSP + lane]      = p0;
            SsF[r * SSP + lane + 32] = p1;
            float sum = p0 + p1;
#pragma unroll
            for (int o = 16; o > 0; o >>= 1)
                sum += __shfl_xor_sync(0xFFFFFFFFu, sum, o);
            float crr = __expf(m_i[rr] - m_new);
            l_i[rr] = l_i[rr] * crr + sum;
            m_i[rr] = m_new;
            if (lane == 0) corr[r] = crr;
        }
        __syncthreads();

        // ---- convert P -> fp16 hi/lo; scale O accumulators ----
#pragma unroll
        for (int j = 0; j < 8; ++j) {
            int i = tid + j * 256;
            int r = i >> 5;
            int c2 = (i & 31) * 2;
            float p0 = SsF[r * SSP + c2];
            float p1 = SsF[r * SSP + c2 + 1];
            __half h0 = __float2half_rn(p0);
            __half h1 = __float2half_rn(p1);
            *(__half2*)(smx + O_PH + r * PPITCH + c2 * 2) = __halves2half2(h0, h1);
            *(__half2*)(smx + O_PL + r * PPITCH + c2 * 2) =
                __halves2half2(__float2half_rn(p0 - __half2float(h0)),
                               __float2half_rn(p1 - __half2float(h1)));
        }
        {
            float cr0 = corr[wr * 16 + (lane >> 2)];
            float cr1 = corr[wr * 16 + (lane >> 2) + 8];
#pragma unroll
            for (int t = 0; t < 8; ++t) {
                oacc[t][0] *= cr0; oacc[t][1] *= cr0;
                oacc[t][2] *= cr1; oacc[t][3] *= cr1;
            }
        }
        __syncthreads();

        // ---- PV: O += Ph*Vh + Pl*Vh ----
        {
            uint32_t pH = sb + O_PH + (wr * 16 + (lane & 15)) * PPITCH + (lane >> 4) * 16;
            uint32_t pL = pH + (O_PL - O_PH);
            uint32_t vHb = sb + O_KV + ATILE + (lane & 15) * APITCH + wc * 128;
#pragma unroll
            for (int s = 0; s < 4; ++s) {
                uint32_t ph4[4], pl4[4];
                ldm_x4(ph4, pH + s * 32);
                ldm_x4(pl4, pL + s * 32);
#pragma unroll
                for (int j = 0; j < 8; ++j) {
                    uint32_t vh2[2];
                    ldm_x2t(vh2, vHb + s * 16 * APITCH + j * 16);
                    mma16816(oacc[j], ph4, vh2[0], vh2[1]);
                    mma16816(oacc[j], pl4, vh2[0], vh2[1]);
                }
            }
        }
    }

    // ---- epilogue ----
    __syncthreads();
    if (lane == 0) {
#pragma unroll
        for (int rr = 0; rr < 8; ++rr)
            linv[warp * 8 + rr] = 1.f / l_i[rr];
    }
    __syncthreads();

    {
        float li0 = linv[wr * 16 + (lane >> 2)];
        float li1 = linv[wr * 16 + (lane >> 2) + 8];
        int orow = qb * 64 + wr * 16 + (lane >> 2);
        int ocol = h * HD + wc * 64 + (lane & 3) * 2;
#pragma unroll
        for (int j = 0; j < 8; ++j) {
            int c = ocol + j * 8;
            *(__half2*)&outH[(size_t)orow * HID + c] =
                __halves2half2(__float2half_rn(oacc[j][0] * li0),
                               __float2half_rn(oacc[j][1] * li0));
            *(__half2*)&outH[(size_t)(orow + 8) * HID + c] =
                __halves2half2(__float2half_rn(oacc[j][2] * li1),
                               __float2half_rn(oacc[j][3] * li1));
        }
    }
}

// ---------------------------------------------------------------------------
// kernel_launch
// ---------------------------------------------------------------------------
extern "C" void kernel_launch(void* const* d_in, const int* in_sizes, int n_in,
                              void* d_out, int out_size)
{
    const float* hs    = (const float*)d_in[0];
    const int*   pos   = (const int*)d_in[1];
    const float* w_qkv = (const float*)d_in[2];
    const float* w_o   = (const float*)d_in[3];
    float* out = (float*)d_out;

    float* qkv; cudaGetSymbolAddress((void**)&qkv, g_qkv);
    __half *Ah, *Bh, *Bh2, *Qh, *Ql, *Kh, *Vh;
    cudaGetSymbolAddress((void**)&Ah, g_Ah);
    cudaGetSymbolAddress((void**)&Bh, g_Bh);
    cudaGetSymbolAddress((void**)&Bh2, g_Bh2);
    cudaGetSymbolAddress((void**)&Qh, g_Qh);
    cudaGetSymbolAddress((void**)&Ql, g_Ql);
    cudaGetSymbolAddress((void**)&Kh, g_Kh);
    cudaGetSymbolAddress((void**)&Vh, g_Vh);

    cudaFuncSetAttribute(gemm_mma_kernel,
                         cudaFuncAttributeMaxDynamicSharedMemorySize, GEMM_SMEM);
    cudaFuncSetAttribute(flash_mma_kernel,
                         cudaFuncAttributeMaxDynamicSharedMemorySize, FL_SMEM);

    // 1) cast hs -> fp16 ; transpose both weight matrices
    cast_kernel<<<(SEQ * HID / 4 + 255) / 256, 256>>>(hs, Ah, SEQ * HID / 4);
    transT_kernel<<<dim3(QKVN / 32, HID / 32), dim3(32, 8)>>>(w_qkv, Bh, HID, QKVN);
    transT_kernel<<<dim3(HID / 32, HID / 32), dim3(32, 8)>>>(w_o, Bh2, HID, HID);

    // 2) QKV projection (tensor cores, pure fp16, 2 CTAs/SM)
    gemm_mma_kernel<<<dim3(QKVN / 128, SEQ / 128), 256, GEMM_SMEM>>>(
        Ah, Bh, qkv, HID, QKVN);

    // 3) RoPE + split into fp16 Q(hi/lo)/K/V [h][s][d]
    {
        int total = SEQ * (NH + 2 * NKV) * (HD / 2);
        rope_split_kernel<<<(total + 255) / 256, 256>>>(qkv, pos, Qh, Ql, Kh, Vh);
    }

    // 4) Tensor-core flash attention (2 CTAs/SM) -> fp16 into Ah
    flash_mma_kernel<<<dim3(SEQ / 64, NH), 256, FL_SMEM>>>(
        Qh, Ql, Kh, Vh, Ah);

    // 5) Output projection (tensor cores, pure fp16, 2 CTAs/SM)
    gemm_mma_kernel<<<dim3(HID / 128, SEQ / 128), 256, GEMM_SMEM>>>(
        Ah, Bh2, out, HID, HID);
}